// round 1
// baseline (speedup 1.0000x reference)
#include <cuda_runtime.h>
#include <cstddef>

#define HG 9
#define WG 25
#define NN 225
#define BATCH 128
#define CIN 2048

// ---------------- scratch (no allocations allowed) ----------------
__device__ float g_fea_part[BATCH * 8 * NN * 8];   // [b][chunk][n][8] partial pool sums
__device__ float g_flat[BATCH * 1800];             // GAT2 output, flattened
__device__ float g_hid[BATCH * 2048];              // fc1 output

// ---------------- kernel 1: 1x1 conv pool (2048 -> 8), channel-chunked ----------------
// grid (128, 8), block 225. Each block handles 256 channels for one batch.
__global__ void pool_kernel(const float* __restrict__ x4, const float* __restrict__ pw) {
    int b = blockIdx.x, cc = blockIdx.y, n = threadIdx.x;
    __shared__ float s_pw[256][8];
    for (int i = threadIdx.x; i < 2048; i += blockDim.x) {
        int c = i >> 3, o = i & 7;
        s_pw[c][o] = pw[o * 2048 + cc * 256 + c];
    }
    __syncthreads();

    const float* xp = x4 + ((size_t)(b * CIN + cc * 256)) * NN + n;
    float acc[8];
#pragma unroll
    for (int o = 0; o < 8; o++) acc[o] = 0.f;

#pragma unroll 8
    for (int c = 0; c < 256; c++) {
        float v = xp[(size_t)c * NN];
        float4 w0 = *(const float4*)&s_pw[c][0];
        float4 w1 = *(const float4*)&s_pw[c][4];
        acc[0] += v * w0.x; acc[1] += v * w0.y; acc[2] += v * w0.z; acc[3] += v * w0.w;
        acc[4] += v * w1.x; acc[5] += v * w1.y; acc[6] += v * w1.z; acc[7] += v * w1.w;
    }
    float* out = g_fea_part + ((size_t)((b * 8 + cc) * NN + n)) * 8;
#pragma unroll
    for (int o = 0; o < 8; o++) out[o] = acc[o];
}

// ---------------- kernel 2: fused GAT1 + GAT2 ----------------
// grid 128 (one block per batch), block 225 (one thread per node).
// Neighbors of the 8-connected grid (incl. self-loop) computed on the fly.
__global__ void gat_kernel(const float* __restrict__ pb,
                           const float* __restrict__ W1, const float* __restrict__ a1s,
                           const float* __restrict__ a1d, const float* __restrict__ b1,
                           const float* __restrict__ W2, const float* __restrict__ a2s,
                           const float* __restrict__ a2d, const float* __restrict__ b2) {
    extern __shared__ float sm[];
    float* h1  = sm;               // [64][225]  transposed: h1[f*225 + n]
    float* h2s = h1 + 64 * NN;     // [225][9]   stride 9 (coprime with 32)
    float* as1 = h2s + NN * 9;     // [225][5]   stride 5 (coprime with 32)
    float* as2 = as1 + NN * 5;     // [225]
    float* W1s = as2 + NN;         // 512
    float* W2s = W1s + 512;        // 512

    int b = blockIdx.x, n = threadIdx.x;
    for (int i = n; i < 512; i += blockDim.x) { W1s[i] = W1[i]; W2s[i] = W2[i]; }

    // fea[n][k] = sum of 8 partial chunks + pool bias
    float fs[8];
#pragma unroll
    for (int k = 0; k < 8; k++) fs[k] = pb[k];
#pragma unroll
    for (int cc = 0; cc < 8; cc++) {
        const float* fp = g_fea_part + ((size_t)((b * 8 + cc) * NN + n)) * 8;
#pragma unroll
        for (int k = 0; k < 8; k++) fs[k] += fp[k];
    }
    __syncthreads();

    // h1 = fea @ W1   (+ attention logits)
    float ad1[4];
    {
        float as[4];
#pragma unroll
        for (int h = 0; h < 4; h++) { as[h] = 0.f; ad1[h] = 0.f; }
#pragma unroll
        for (int f = 0; f < 64; f++) {
            float hv = 0.f;
#pragma unroll
            for (int k = 0; k < 8; k++) hv += fs[k] * W1s[k * 64 + f];
            h1[f * NN + n] = hv;
            int hd = f >> 4;
            as[hd] += hv * __ldg(&a1s[f]);
            ad1[hd] += hv * __ldg(&a1d[f]);
        }
#pragma unroll
        for (int h = 0; h < 4; h++) as1[n * 5 + h] = as[h];
    }
    __syncthreads();

    // neighbor enumeration (fixed 9, invalid masked with -1e30)
    int i = n / WG, j = n % WG;
    int srcs[9]; float mask[9];
#pragma unroll
    for (int k = 0; k < 9; k++) {
        int di = k / 3 - 1, dj = k % 3 - 1;
        int ni = i + di, nj = j + dj;
        bool v = (ni >= 0 && ni < HG && nj >= 0 && nj < WG);
        srcs[k] = v ? ni * WG + nj : n;
        mask[k] = v ? 0.f : -1e30f;
    }

    // GAT1 attention + aggregation, fused with bias+relu+W2 -> h2 (per node, in regs)
    float h2[8];
#pragma unroll
    for (int o = 0; o < 8; o++) h2[o] = 0.f;

#pragma unroll
    for (int hd = 0; hd < 4; hd++) {
        float ek[9], m = -1e30f;
#pragma unroll
        for (int k = 0; k < 9; k++) {
            float e = as1[srcs[k] * 5 + hd] + ad1[hd];
            e = e > 0.f ? e : 0.2f * e;   // leaky relu 0.2
            e += mask[k];
            ek[k] = e; m = fmaxf(m, e);
        }
        float s = 0.f;
#pragma unroll
        for (int k = 0; k < 9; k++) { ek[k] = __expf(ek[k] - m); s += ek[k]; }
        float inv = 1.f / s;

        float acc[16];
#pragma unroll
        for (int d = 0; d < 16; d++) acc[d] = 0.f;
#pragma unroll
        for (int k = 0; k < 9; k++) {
            float w = ek[k] * inv;
            const float* hp = &h1[(hd * 16) * NN + srcs[k]];
#pragma unroll
            for (int d = 0; d < 16; d++) acc[d] += w * hp[d * NN];
        }
#pragma unroll
        for (int d = 0; d < 16; d++) {
            int f = hd * 16 + d;
            float x1 = fmaxf(acc[d] + __ldg(&b1[f]), 0.f);   // relu(GAT1 + bias)
#pragma unroll
            for (int o = 0; o < 8; o++) h2[o] += x1 * W2s[f * 8 + o];
        }
    }

    // publish h2 + GAT2 logits
    float ad2 = 0.f;
    {
        float a = 0.f;
#pragma unroll
        for (int o = 0; o < 8; o++) {
            h2s[n * 9 + o] = h2[o];
            a   += h2[o] * __ldg(&a2s[o]);
            ad2 += h2[o] * __ldg(&a2d[o]);
        }
        as2[n] = a;
    }
    __syncthreads();

    // GAT2 attention + aggregation (heads=1, d=8; mean over 1 head = identity)
    {
        float ek[9], m = -1e30f;
#pragma unroll
        for (int k = 0; k < 9; k++) {
            float e = as2[srcs[k]] + ad2;
            e = e > 0.f ? e : 0.2f * e;
            e += mask[k];
            ek[k] = e; m = fmaxf(m, e);
        }
        float s = 0.f;
#pragma unroll
        for (int k = 0; k < 9; k++) { ek[k] = __expf(ek[k] - m); s += ek[k]; }
        float inv = 1.f / s;

        float acc2[8];
#pragma unroll
        for (int o = 0; o < 8; o++) acc2[o] = 0.f;
#pragma unroll
        for (int k = 0; k < 9; k++) {
            float w = ek[k] * inv;
            const float* hp = &h2s[srcs[k] * 9];
#pragma unroll
            for (int o = 0; o < 8; o++) acc2[o] += w * hp[o];
        }
        float* fo = g_flat + (size_t)b * 1800 + n * 8;
#pragma unroll
        for (int o = 0; o < 8; o++) fo[o] = acc2[o] + __ldg(&b2[o]);
    }
}

// ---------------- kernels 3/4: tiled fp32 GEMM, C = act(A@W + bias) ----------------
// 64x64 tile, TK=8, 256 threads, 4x4 microtile, register prefetch.
template <int RELU>
__global__ void gemm_kernel(const float* __restrict__ A, const float* __restrict__ W,
                            const float* __restrict__ bias, float* __restrict__ C,
                            int K, int N) {
    __shared__ float As[8][68];
    __shared__ float Bs[8][68];
    int col0 = blockIdx.x * 64, row0 = blockIdx.y * 64;
    int t = threadIdx.x;
    int tx = t & 15, ty = t >> 4;

    float acc[4][4];
#pragma unroll
    for (int i = 0; i < 4; i++)
#pragma unroll
        for (int j = 0; j < 4; j++) acc[i][j] = 0.f;

    int am = t >> 2, ak = (t & 3) * 2;   // A tile: 64 rows x 8 k, float2 along k
    int bk = t >> 5, bn = (t & 31) * 2;  // W tile: 8 k x 64 n, float2 along n
    const float* Ap = A + (size_t)(row0 + am) * K + ak;
    const float* Wp = W + (size_t)bk * N + col0 + bn;

    float2 av = *(const float2*)Ap;
    float2 bv = *(const float2*)Wp;

    for (int kt = 0; kt < K; kt += 8) {
        As[ak][am] = av.x;
        As[ak + 1][am] = av.y;
        *(float2*)&Bs[bk][bn] = bv;
        __syncthreads();

        if (kt + 8 < K) {
            av = *(const float2*)(Ap + kt + 8);
            bv = *(const float2*)(Wp + (size_t)(kt + 8) * N);
        }
#pragma unroll
        for (int k = 0; k < 8; k++) {
            float4 a4 = *(const float4*)&As[k][ty * 4];
            float4 b4 = *(const float4*)&Bs[k][tx * 4];
            float ar[4] = {a4.x, a4.y, a4.z, a4.w};
            float br[4] = {b4.x, b4.y, b4.z, b4.w};
#pragma unroll
            for (int i2 = 0; i2 < 4; i2++)
#pragma unroll
                for (int j2 = 0; j2 < 4; j2++) acc[i2][j2] += ar[i2] * br[j2];
        }
        __syncthreads();
    }

#pragma unroll
    for (int i2 = 0; i2 < 4; i2++) {
        float4 ov;
        float* op = (float*)&ov;
#pragma unroll
        for (int j2 = 0; j2 < 4; j2++) {
            float v = acc[i2][j2] + bias[col0 + tx * 4 + j2];
            if (RELU) v = fmaxf(v, 0.f);
            op[j2] = v;
        }
        *(float4*)&C[(size_t)(row0 + ty * 4 + i2) * N + col0 + tx * 4] = ov;
    }
}

// ---------------- launcher ----------------
extern "C" void kernel_launch(void* const* d_in, const int* in_sizes, int n_in,
                              void* d_out, int out_size) {
    const float* x4     = (const float*)d_in[0];
    const float* pool_w = (const float*)d_in[1];
    const float* pool_b = (const float*)d_in[2];
    const float* g1w    = (const float*)d_in[3];
    const float* g1as   = (const float*)d_in[4];
    const float* g1ad   = (const float*)d_in[5];
    const float* g1b    = (const float*)d_in[6];
    const float* g2w    = (const float*)d_in[7];
    const float* g2as   = (const float*)d_in[8];
    const float* g2ad   = (const float*)d_in[9];
    const float* g2b    = (const float*)d_in[10];
    const float* w1     = (const float*)d_in[11];
    const float* b1     = (const float*)d_in[12];
    const float* w2     = (const float*)d_in[13];
    const float* b2     = (const float*)d_in[14];
    float* out = (float*)d_out;

    // dynamic smem for the fused GAT kernel: 64*225 + 225*9 + 225*5 + 225 + 1024 floats
    const int gat_smem = (64 * NN + NN * 9 + NN * 5 + NN + 1024) * (int)sizeof(float);
    cudaFuncSetAttribute(gat_kernel, cudaFuncAttributeMaxDynamicSharedMemorySize, gat_smem);

    float *flatp, *hidp;
    cudaGetSymbolAddress((void**)&flatp, g_flat);
    cudaGetSymbolAddress((void**)&hidp, g_hid);

    pool_kernel<<<dim3(128, 8), 225>>>(x4, pool_w);
    gat_kernel<<<128, 225, gat_smem>>>(pool_b, g1w, g1as, g1ad, g1b, g2w, g2as, g2ad, g2b);
    gemm_kernel<1><<<dim3(32, 2), 256>>>(flatp, w1, b1, hidp, 1800, 2048);
    gemm_kernel<0><<<dim3(325, 2), 256>>>(hidp, w2, b2, out, 2048, 20800);
}

// round 3
// speedup vs baseline: 1.9505x; 1.9505x over previous
#include <cuda_runtime.h>
#include <cuda_bf16.h>
#include <cstdint>
#include <cstddef>

#define HG 9
#define WG 25
#define NN 225
#define BATCH 128
#define CIN 2048

#define KPAD1 1856   // 58 * 32
#define NITER1 58
#define K2 2048
#define NITER2 64
#define N1 2048
#define N2 20800

// ---------------- scratch ----------------
__device__ __align__(16) float g_fea_part[BATCH * 16 * NN * 8];
__device__ __align__(16) __nv_bfloat16 g_flat_hi[BATCH * KPAD1];
__device__ __align__(16) __nv_bfloat16 g_flat_lo[BATCH * KPAD1];
__device__ __align__(16) __nv_bfloat16 g_hid_hi[BATCH * K2];
__device__ __align__(16) __nv_bfloat16 g_hid_lo[BATCH * K2];

__device__ __forceinline__ uint32_t smem_u32(const void* p) {
    uint32_t a;
    asm("{ .reg .u64 t; cvta.to.shared.u64 t, %1; cvt.u32.u64 %0, t; }" : "=r"(a) : "l"(p));
    return a;
}

// ---------------- kernel 1: pool (2048 -> 8), 128-channel chunks ----------------
__global__ void pool_kernel(const float* __restrict__ x4, const float* __restrict__ pw) {
    int b = blockIdx.x, cc = blockIdx.y, n = threadIdx.x;
    __shared__ float s_pw[128][8];
    for (int i = threadIdx.x; i < 1024; i += blockDim.x) {
        int c = i >> 3, o = i & 7;
        s_pw[c][o] = pw[o * 2048 + cc * 128 + c];
    }
    __syncthreads();

    const float* xp = x4 + ((size_t)(b * CIN + cc * 128)) * NN + n;
    float acc[8];
#pragma unroll
    for (int o = 0; o < 8; o++) acc[o] = 0.f;

#pragma unroll 16
    for (int c = 0; c < 128; c++) {
        float v = xp[(size_t)c * NN];
        float4 w0 = *(const float4*)&s_pw[c][0];
        float4 w1 = *(const float4*)&s_pw[c][4];
        acc[0] += v * w0.x; acc[1] += v * w0.y; acc[2] += v * w0.z; acc[3] += v * w0.w;
        acc[4] += v * w1.x; acc[5] += v * w1.y; acc[6] += v * w1.z; acc[7] += v * w1.w;
    }
    float* out = g_fea_part + ((size_t)((b * 16 + cc) * NN + n)) * 8;
#pragma unroll
    for (int o = 0; o < 8; o++) out[o] = acc[o];
}

// ---------------- kernel 2: fused GAT1 + GAT2 -> bf16 hi/lo flat ----------------
__global__ void gat_kernel(const float* __restrict__ pb,
                           const float* __restrict__ W1, const float* __restrict__ a1s,
                           const float* __restrict__ a1d, const float* __restrict__ b1,
                           const float* __restrict__ W2, const float* __restrict__ a2s,
                           const float* __restrict__ a2d, const float* __restrict__ b2) {
    extern __shared__ float sm[];
    float* h1  = sm;               // [64][225]
    float* h2s = h1 + 64 * NN;     // [225][9]
    float* as1 = h2s + NN * 9;     // [225][5]
    float* as2 = as1 + NN * 5;     // [225]
    float* W1s = as2 + NN;         // 512
    float* W2s = W1s + 512;        // 512

    int b = blockIdx.x, n = threadIdx.x;
    for (int i = n; i < 512; i += blockDim.x) { W1s[i] = W1[i]; W2s[i] = W2[i]; }

    float fs[8];
#pragma unroll
    for (int k = 0; k < 8; k++) fs[k] = pb[k];
#pragma unroll
    for (int cc = 0; cc < 16; cc++) {
        const float* fp = g_fea_part + ((size_t)((b * 16 + cc) * NN + n)) * 8;
#pragma unroll
        for (int k = 0; k < 8; k++) fs[k] += fp[k];
    }
    __syncthreads();

    float ad1[4];
    {
        float as[4];
#pragma unroll
        for (int h = 0; h < 4; h++) { as[h] = 0.f; ad1[h] = 0.f; }
#pragma unroll
        for (int f = 0; f < 64; f++) {
            float hv = 0.f;
#pragma unroll
            for (int k = 0; k < 8; k++) hv += fs[k] * W1s[k * 64 + f];
            h1[f * NN + n] = hv;
            int hd = f >> 4;
            as[hd] += hv * __ldg(&a1s[f]);
            ad1[hd] += hv * __ldg(&a1d[f]);
        }
#pragma unroll
        for (int h = 0; h < 4; h++) as1[n * 5 + h] = as[h];
    }
    __syncthreads();

    int i = n / WG, j = n % WG;
    int srcs[9]; float mask[9];
#pragma unroll
    for (int k = 0; k < 9; k++) {
        int di = k / 3 - 1, dj = k % 3 - 1;
        int ni = i + di, nj = j + dj;
        bool v = (ni >= 0 && ni < HG && nj >= 0 && nj < WG);
        srcs[k] = v ? ni * WG + nj : n;
        mask[k] = v ? 0.f : -1e30f;
    }

    float h2[8];
#pragma unroll
    for (int o = 0; o < 8; o++) h2[o] = 0.f;

#pragma unroll
    for (int hd = 0; hd < 4; hd++) {
        float ek[9], m = -1e30f;
#pragma unroll
        for (int k = 0; k < 9; k++) {
            float e = as1[srcs[k] * 5 + hd] + ad1[hd];
            e = e > 0.f ? e : 0.2f * e;
            e += mask[k];
            ek[k] = e; m = fmaxf(m, e);
        }
        float s = 0.f;
#pragma unroll
        for (int k = 0; k < 9; k++) { ek[k] = __expf(ek[k] - m); s += ek[k]; }
        float inv = 1.f / s;

        float acc[16];
#pragma unroll
        for (int d = 0; d < 16; d++) acc[d] = 0.f;
#pragma unroll
        for (int k = 0; k < 9; k++) {
            float w = ek[k] * inv;
            const float* hp = &h1[(hd * 16) * NN + srcs[k]];
#pragma unroll
            for (int d = 0; d < 16; d++) acc[d] += w * hp[d * NN];
        }
#pragma unroll
        for (int d = 0; d < 16; d++) {
            int f = hd * 16 + d;
            float x1 = fmaxf(acc[d] + __ldg(&b1[f]), 0.f);
#pragma unroll
            for (int o = 0; o < 8; o++) h2[o] += x1 * W2s[f * 8 + o];
        }
    }

    float ad2 = 0.f;
    {
        float a = 0.f;
#pragma unroll
        for (int o = 0; o < 8; o++) {
            h2s[n * 9 + o] = h2[o];
            a   += h2[o] * __ldg(&a2s[o]);
            ad2 += h2[o] * __ldg(&a2d[o]);
        }
        as2[n] = a;
    }
    __syncthreads();

    {
        float ek[9], m = -1e30f;
#pragma unroll
        for (int k = 0; k < 9; k++) {
            float e = as2[srcs[k]] + ad2;
            e = e > 0.f ? e : 0.2f * e;
            e += mask[k];
            ek[k] = e; m = fmaxf(m, e);
        }
        float s = 0.f;
#pragma unroll
        for (int k = 0; k < 9; k++) { ek[k] = __expf(ek[k] - m); s += ek[k]; }
        float inv = 1.f / s;

        float acc2[8];
#pragma unroll
        for (int o = 0; o < 8; o++) acc2[o] = 0.f;
#pragma unroll
        for (int k = 0; k < 9; k++) {
            float w = ek[k] * inv;
            const float* hp = &h2s[srcs[k] * 9];
#pragma unroll
            for (int o = 0; o < 8; o++) acc2[o] += w * hp[o];
        }
        size_t base = (size_t)b * KPAD1 + n * 8;
#pragma unroll
        for (int o = 0; o < 8; o++) {
            float v = acc2[o] + __ldg(&b2[o]);
            __nv_bfloat16 hi = __float2bfloat16(v);
            g_flat_hi[base + o] = hi;
            g_flat_lo[base + o] = __float2bfloat16(v - __bfloat162float(hi));
        }
        if (n < 56) {
            __nv_bfloat16 z = __float2bfloat16(0.f);
            g_flat_hi[(size_t)b * KPAD1 + 1800 + n] = z;
            g_flat_lo[(size_t)b * KPAD1 + 1800 + n] = z;
        }
    }
}

// ---------------- HMMA GEMM via mma.sync bf16 (3-pass hi/lo split) ----------------
// C[128, N] = A[128, K] @ B[K, N] (+bias, relu). A preconverted bf16 hi/lo,
// B fp32 converted to hi/lo in smem. Block: 128x64 tile, BK=32, 8 warps.
// Smem (bytes): per buffer: Ahi 128*80, Alo 128*80, Bhi 32*144, Blo 32*144.
#define A_STR 80
#define B_STR 144
#define BUF_SZ (128 * A_STR * 2 + 32 * B_STR * 2)      // 29696
#define OFF_AHI(b) ((b) * BUF_SZ)
#define OFF_ALO(b) ((b) * BUF_SZ + 128 * A_STR)
#define OFF_BHI(b) ((b) * BUF_SZ + 128 * A_STR * 2)
#define OFF_BLO(b) ((b) * BUF_SZ + 128 * A_STR * 2 + 32 * B_STR)
#define GEMM_SMEM (2 * BUF_SZ)                          // 59392

__device__ __forceinline__ void ldm_x4(uint32_t* r, uint32_t addr) {
    asm volatile("ldmatrix.sync.aligned.m8n8.x4.shared.b16 {%0,%1,%2,%3}, [%4];"
                 : "=r"(r[0]), "=r"(r[1]), "=r"(r[2]), "=r"(r[3]) : "r"(addr));
}
__device__ __forceinline__ void ldm_x4t(uint32_t* r, uint32_t addr) {
    asm volatile("ldmatrix.sync.aligned.m8n8.x4.trans.shared.b16 {%0,%1,%2,%3}, [%4];"
                 : "=r"(r[0]), "=r"(r[1]), "=r"(r[2]), "=r"(r[3]) : "r"(addr));
}
__device__ __forceinline__ void mma16816(float* c, const uint32_t* a, uint32_t b0, uint32_t b1) {
    asm volatile("mma.sync.aligned.m16n8k16.row.col.f32.bf16.bf16.f32 "
                 "{%0,%1,%2,%3}, {%4,%5,%6,%7}, {%8,%9}, {%0,%1,%2,%3};"
                 : "+f"(c[0]), "+f"(c[1]), "+f"(c[2]), "+f"(c[3])
                 : "r"(a[0]), "r"(a[1]), "r"(a[2]), "r"(a[3]), "r"(b0), "r"(b1));
}
__device__ __forceinline__ uint2 pack_hi(float4 v, float4* rem) {
    union { __nv_bfloat16 h[4]; uint2 u; } p;
    p.h[0] = __float2bfloat16(v.x); p.h[1] = __float2bfloat16(v.y);
    p.h[2] = __float2bfloat16(v.z); p.h[3] = __float2bfloat16(v.w);
    rem->x = v.x - __bfloat162float(p.h[0]); rem->y = v.y - __bfloat162float(p.h[1]);
    rem->z = v.z - __bfloat162float(p.h[2]); rem->w = v.w - __bfloat162float(p.h[3]);
    return p.u;
}

template <bool RELU, bool SPLIT_OUT>
__global__ void __launch_bounds__(256) mma_gemm(
    const __nv_bfloat16* __restrict__ Ahi, const __nv_bfloat16* __restrict__ Alo, int lda,
    const float* __restrict__ B, int ldb, int Krows, int niter,
    const float* __restrict__ bias,
    float* __restrict__ Cf, __nv_bfloat16* __restrict__ Chi, __nv_bfloat16* __restrict__ Clo,
    int ldc) {
    extern __shared__ char smc[];
    uint32_t sb = smem_u32(smc);
    int t = threadIdx.x, wid = t >> 5, lane = t & 31;
    int n0_blk = blockIdx.x * 64;

    // loader maps
    int arow = t >> 2, aseg = t & 3;           // A: rows 0..63 (+64), seg*16B
    int brow = t >> 4, bcol = (t & 15) * 4;    // B: rows 0..15 (+16), 4 floats

    float acc[32];
#pragma unroll
    for (int c = 0; c < 32; c++) acc[c] = 0.f;

    uint4 pa_h[2], pa_l[2];
    float4 pb[2];

    // prefetch iteration 0
    {
        const char* gh = (const char*)(Ahi + (size_t)arow * lda) + aseg * 16;
        const char* gl = (const char*)(Alo + (size_t)arow * lda) + aseg * 16;
        pa_h[0] = *(const uint4*)gh;
        pa_h[1] = *(const uint4*)(gh + (size_t)64 * lda * 2);
        pa_l[0] = *(const uint4*)gl;
        pa_l[1] = *(const uint4*)(gl + (size_t)64 * lda * 2);
#pragma unroll
        for (int half = 0; half < 2; half++) {
            int kg = brow + half * 16;
            pb[half] = (kg < Krows) ? *(const float4*)(B + (size_t)kg * ldb + n0_blk + bcol)
                                    : make_float4(0.f, 0.f, 0.f, 0.f);
        }
    }
    // store iteration 0
    {
        *(uint4*)(smc + OFF_AHI(0) + arow * A_STR + aseg * 16) = pa_h[0];
        *(uint4*)(smc + OFF_AHI(0) + (arow + 64) * A_STR + aseg * 16) = pa_h[1];
        *(uint4*)(smc + OFF_ALO(0) + arow * A_STR + aseg * 16) = pa_l[0];
        *(uint4*)(smc + OFF_ALO(0) + (arow + 64) * A_STR + aseg * 16) = pa_l[1];
#pragma unroll
        for (int half = 0; half < 2; half++) {
            float4 rem;
            uint2 hu = pack_hi(pb[half], &rem);
            union { __nv_bfloat16 h[4]; uint2 u; } lu;
            lu.h[0] = __float2bfloat16(rem.x); lu.h[1] = __float2bfloat16(rem.y);
            lu.h[2] = __float2bfloat16(rem.z); lu.h[3] = __float2bfloat16(rem.w);
            *(uint2*)(smc + OFF_BHI(0) + (brow + half * 16) * B_STR + bcol * 2) = hu;
            *(uint2*)(smc + OFF_BLO(0) + (brow + half * 16) * B_STR + bcol * 2) = lu.u;
        }
    }
    __syncthreads();

    int m0 = wid * 16;
    int lrow = lane & 15, lcolsel = lane >> 4;

    for (int it = 0; it < niter; it++) {
        int buf = it & 1;
        // prefetch it+1
        if (it + 1 < niter) {
            int k0 = (it + 1) * 32;
            const char* gh = (const char*)(Ahi + (size_t)arow * lda + k0) + aseg * 16;
            const char* gl = (const char*)(Alo + (size_t)arow * lda + k0) + aseg * 16;
            pa_h[0] = *(const uint4*)gh;
            pa_h[1] = *(const uint4*)(gh + (size_t)64 * lda * 2);
            pa_l[0] = *(const uint4*)gl;
            pa_l[1] = *(const uint4*)(gl + (size_t)64 * lda * 2);
#pragma unroll
            for (int half = 0; half < 2; half++) {
                int kg = k0 + brow + half * 16;
                pb[half] = (kg < Krows) ? *(const float4*)(B + (size_t)kg * ldb + n0_blk + bcol)
                                        : make_float4(0.f, 0.f, 0.f, 0.f);
            }
        }

        // compute on buf
        uint32_t abase_h = sb + OFF_AHI(buf) + (m0 + lrow) * A_STR + lcolsel * 16;
        uint32_t abase_l = sb + OFF_ALO(buf) + (m0 + lrow) * A_STR + lcolsel * 16;
#pragma unroll
        for (int ks = 0; ks < 2; ks++) {
            uint32_t ah[4], al[4];
            ldm_x4(ah, abase_h + ks * 32);
            ldm_x4(al, abase_l + ks * 32);
            uint32_t bbase_h = sb + OFF_BHI(buf) + (ks * 16 + lrow) * B_STR + lcolsel * 16;
            uint32_t bbase_l = sb + OFF_BLO(buf) + (ks * 16 + lrow) * B_STR + lcolsel * 16;
#pragma unroll
            for (int jj = 0; jj < 4; jj++) {
                uint32_t bh[4], bl[4];
                ldm_x4t(bh, bbase_h + jj * 32);
                ldm_x4t(bl, bbase_l + jj * 32);
                float* c0 = acc + (jj * 2) * 4;
                float* c1 = acc + (jj * 2 + 1) * 4;
                mma16816(c0, ah, bh[0], bh[1]);
                mma16816(c1, ah, bh[2], bh[3]);
                mma16816(c0, ah, bl[0], bl[1]);
                mma16816(c1, ah, bl[2], bl[3]);
                mma16816(c0, al, bh[0], bh[1]);
                mma16816(c1, al, bh[2], bh[3]);
            }
        }

        // store prefetched to other buffer
        if (it + 1 < niter) {
            int nb = buf ^ 1;
            *(uint4*)(smc + OFF_AHI(nb) + arow * A_STR + aseg * 16) = pa_h[0];
            *(uint4*)(smc + OFF_AHI(nb) + (arow + 64) * A_STR + aseg * 16) = pa_h[1];
            *(uint4*)(smc + OFF_ALO(nb) + arow * A_STR + aseg * 16) = pa_l[0];
            *(uint4*)(smc + OFF_ALO(nb) + (arow + 64) * A_STR + aseg * 16) = pa_l[1];
#pragma unroll
            for (int half = 0; half < 2; half++) {
                float4 rem;
                uint2 hu = pack_hi(pb[half], &rem);
                union { __nv_bfloat16 h[4]; uint2 u; } lu;
                lu.h[0] = __float2bfloat16(rem.x); lu.h[1] = __float2bfloat16(rem.y);
                lu.h[2] = __float2bfloat16(rem.z); lu.h[3] = __float2bfloat16(rem.w);
                *(uint2*)(smc + OFF_BHI(nb) + (brow + half * 16) * B_STR + bcol * 2) = hu;
                *(uint2*)(smc + OFF_BLO(nb) + (brow + half * 16) * B_STR + bcol * 2) = lu.u;
            }
        }
        __syncthreads();
    }

    // ---------------- epilogue ----------------
    int g = lane >> 2, tg = lane & 3;
#pragma unroll
    for (int j = 0; j < 8; j++) {
        int nb = n0_blk + j * 8 + tg * 2;
        float bs0 = __ldg(&bias[nb]), bs1 = __ldg(&bias[nb + 1]);
#pragma unroll
        for (int half = 0; half < 2; half++) {   // rows g and g+8
            int m = m0 + g + half * 8;
            float v0 = acc[j * 4 + half * 2 + 0] + bs0;
            float v1 = acc[j * 4 + half * 2 + 1] + bs1;
            if (RELU) { v0 = fmaxf(v0, 0.f); v1 = fmaxf(v1, 0.f); }
            if (SPLIT_OUT) {
                size_t o = (size_t)m * ldc + nb;
                __nv_bfloat16 h0 = __float2bfloat16(v0), h1 = __float2bfloat16(v1);
                Chi[o] = h0; Chi[o + 1] = h1;
                Clo[o] = __float2bfloat16(v0 - __bfloat162float(h0));
                Clo[o + 1] = __float2bfloat16(v1 - __bfloat162float(h1));
            } else {
                size_t o = (size_t)m * ldc + nb;
                Cf[o] = v0; Cf[o + 1] = v1;
            }
        }
    }
}

// ---------------- launcher ----------------
extern "C" void kernel_launch(void* const* d_in, const int* in_sizes, int n_in,
                              void* d_out, int out_size) {
    const float* x4     = (const float*)d_in[0];
    const float* pool_w = (const float*)d_in[1];
    const float* pool_b = (const float*)d_in[2];
    const float* g1w    = (const float*)d_in[3];
    const float* g1as   = (const float*)d_in[4];
    const float* g1ad   = (const float*)d_in[5];
    const float* g1b    = (const float*)d_in[6];
    const float* g2w    = (const float*)d_in[7];
    const float* g2as   = (const float*)d_in[8];
    const float* g2ad   = (const float*)d_in[9];
    const float* g2b    = (const float*)d_in[10];
    const float* w1     = (const float*)d_in[11];
    const float* b1     = (const float*)d_in[12];
    const float* w2     = (const float*)d_in[13];
    const float* b2     = (const float*)d_in[14];
    float* out = (float*)d_out;

    const int gat_smem = (64 * NN + NN * 9 + NN * 5 + NN + 1024) * (int)sizeof(float);
    cudaFuncSetAttribute(gat_kernel, cudaFuncAttributeMaxDynamicSharedMemorySize, gat_smem);
    cudaFuncSetAttribute(mma_gemm<true, true>, cudaFuncAttributeMaxDynamicSharedMemorySize, GEMM_SMEM);
    cudaFuncSetAttribute(mma_gemm<false, false>, cudaFuncAttributeMaxDynamicSharedMemorySize, GEMM_SMEM);

    __nv_bfloat16 *fhi, *flo, *hhi, *hlo;
    cudaGetSymbolAddress((void**)&fhi, g_flat_hi);
    cudaGetSymbolAddress((void**)&flo, g_flat_lo);
    cudaGetSymbolAddress((void**)&hhi, g_hid_hi);
    cudaGetSymbolAddress((void**)&hlo, g_hid_lo);

    pool_kernel<<<dim3(128, 16), 225>>>(x4, pool_w);
    gat_kernel<<<128, 225, gat_smem>>>(pool_b, g1w, g1as, g1ad, g1b, g2w, g2as, g2ad, g2b);
    mma_gemm<true, true><<<N1 / 64, 256, GEMM_SMEM>>>(fhi, flo, KPAD1, w1, N1, 1800, NITER1,
                                                      b1, nullptr, hhi, hlo, N1);
    mma_gemm<false, false><<<N2 / 64, 256, GEMM_SMEM>>>(hhi, hlo, K2, w2, N2, K2, NITER2,
                                                        b2, out, nullptr, nullptr, N2);
}

// round 4
// speedup vs baseline: 2.1329x; 1.0935x over previous
#include <cuda_runtime.h>
#include <cuda_bf16.h>
#include <cstdint>
#include <cstddef>

#define HG 9
#define WG 25
#define NN 225
#define BATCH 128
#define CIN 2048

#define KPAD1 1856   // 58 * 32
#define NITER1 58
#define K2 2048
#define NITER2 64
#define N1 2048
#define N2 20800
#define SPLITS 8

// ---------------- scratch ----------------
__device__ __align__(16) float g_fea_part[BATCH * 16 * NN * 8];
__device__ __align__(16) __nv_bfloat16 g_flat_hi[BATCH * KPAD1];
__device__ __align__(16) __nv_bfloat16 g_flat_lo[BATCH * KPAD1];
__device__ __align__(16) __nv_bfloat16 g_hid_hi[BATCH * K2];
__device__ __align__(16) __nv_bfloat16 g_hid_lo[BATCH * K2];
__device__ __align__(16) float g_part[SPLITS * BATCH * N1];   // fc1 split-K partials

__device__ __forceinline__ uint32_t smem_u32(const void* p) {
    uint32_t a;
    asm("{ .reg .u64 t; cvta.to.shared.u64 t, %1; cvt.u32.u64 %0, t; }" : "=r"(a) : "l"(p));
    return a;
}

// ---------------- kernel 1: pool (unchanged, known good) ----------------
__global__ void pool_kernel(const float* __restrict__ x4, const float* __restrict__ pw) {
    int b = blockIdx.x, cc = blockIdx.y, n = threadIdx.x;
    __shared__ float s_pw[128][8];
    for (int i = threadIdx.x; i < 1024; i += blockDim.x) {
        int c = i >> 3, o = i & 7;
        s_pw[c][o] = pw[o * 2048 + cc * 128 + c];
    }
    __syncthreads();

    const float* xp = x4 + ((size_t)(b * CIN + cc * 128)) * NN + n;
    float acc[8];
#pragma unroll
    for (int o = 0; o < 8; o++) acc[o] = 0.f;

#pragma unroll 16
    for (int c = 0; c < 128; c++) {
        float v = xp[(size_t)c * NN];
        float4 w0 = *(const float4*)&s_pw[c][0];
        float4 w1 = *(const float4*)&s_pw[c][4];
        acc[0] += v * w0.x; acc[1] += v * w0.y; acc[2] += v * w0.z; acc[3] += v * w0.w;
        acc[4] += v * w1.x; acc[5] += v * w1.y; acc[6] += v * w1.z; acc[7] += v * w1.w;
    }
    float* out = g_fea_part + ((size_t)((b * 16 + cc) * NN + n)) * 8;
#pragma unroll
    for (int o = 0; o < 8; o++) out[o] = acc[o];
}

// ---------------- kernel 2: fused GAT1 + GAT2 (unchanged) ----------------
__global__ void gat_kernel(const float* __restrict__ pb,
                           const float* __restrict__ W1, const float* __restrict__ a1s,
                           const float* __restrict__ a1d, const float* __restrict__ b1,
                           const float* __restrict__ W2, const float* __restrict__ a2s,
                           const float* __restrict__ a2d, const float* __restrict__ b2) {
    extern __shared__ float sm[];
    float* h1  = sm;               // [64][225]
    float* h2s = h1 + 64 * NN;     // [225][9]
    float* as1 = h2s + NN * 9;     // [225][5]
    float* as2 = as1 + NN * 5;     // [225]
    float* W1s = as2 + NN;         // 512
    float* W2s = W1s + 512;        // 512

    int b = blockIdx.x, n = threadIdx.x;
    for (int i = n; i < 512; i += blockDim.x) { W1s[i] = W1[i]; W2s[i] = W2[i]; }

    float fs[8];
#pragma unroll
    for (int k = 0; k < 8; k++) fs[k] = pb[k];
#pragma unroll
    for (int cc = 0; cc < 16; cc++) {
        const float* fp = g_fea_part + ((size_t)((b * 16 + cc) * NN + n)) * 8;
#pragma unroll
        for (int k = 0; k < 8; k++) fs[k] += fp[k];
    }
    __syncthreads();

    float ad1[4];
    {
        float as[4];
#pragma unroll
        for (int h = 0; h < 4; h++) { as[h] = 0.f; ad1[h] = 0.f; }
#pragma unroll
        for (int f = 0; f < 64; f++) {
            float hv = 0.f;
#pragma unroll
            for (int k = 0; k < 8; k++) hv += fs[k] * W1s[k * 64 + f];
            h1[f * NN + n] = hv;
            int hd = f >> 4;
            as[hd] += hv * __ldg(&a1s[f]);
            ad1[hd] += hv * __ldg(&a1d[f]);
        }
#pragma unroll
        for (int h = 0; h < 4; h++) as1[n * 5 + h] = as[h];
    }
    __syncthreads();

    int i = n / WG, j = n % WG;
    int srcs[9]; float mask[9];
#pragma unroll
    for (int k = 0; k < 9; k++) {
        int di = k / 3 - 1, dj = k % 3 - 1;
        int ni = i + di, nj = j + dj;
        bool v = (ni >= 0 && ni < HG && nj >= 0 && nj < WG);
        srcs[k] = v ? ni * WG + nj : n;
        mask[k] = v ? 0.f : -1e30f;
    }

    float h2[8];
#pragma unroll
    for (int o = 0; o < 8; o++) h2[o] = 0.f;

#pragma unroll
    for (int hd = 0; hd < 4; hd++) {
        float ek[9], m = -1e30f;
#pragma unroll
        for (int k = 0; k < 9; k++) {
            float e = as1[srcs[k] * 5 + hd] + ad1[hd];
            e = e > 0.f ? e : 0.2f * e;
            e += mask[k];
            ek[k] = e; m = fmaxf(m, e);
        }
        float s = 0.f;
#pragma unroll
        for (int k = 0; k < 9; k++) { ek[k] = __expf(ek[k] - m); s += ek[k]; }
        float inv = 1.f / s;

        float acc[16];
#pragma unroll
        for (int d = 0; d < 16; d++) acc[d] = 0.f;
#pragma unroll
        for (int k = 0; k < 9; k++) {
            float w = ek[k] * inv;
            const float* hp = &h1[(hd * 16) * NN + srcs[k]];
#pragma unroll
            for (int d = 0; d < 16; d++) acc[d] += w * hp[d * NN];
        }
#pragma unroll
        for (int d = 0; d < 16; d++) {
            int f = hd * 16 + d;
            float x1 = fmaxf(acc[d] + __ldg(&b1[f]), 0.f);
#pragma unroll
            for (int o = 0; o < 8; o++) h2[o] += x1 * W2s[f * 8 + o];
        }
    }

    float ad2 = 0.f;
    {
        float a = 0.f;
#pragma unroll
        for (int o = 0; o < 8; o++) {
            h2s[n * 9 + o] = h2[o];
            a   += h2[o] * __ldg(&a2s[o]);
            ad2 += h2[o] * __ldg(&a2d[o]);
        }
        as2[n] = a;
    }
    __syncthreads();

    {
        float ek[9], m = -1e30f;
#pragma unroll
        for (int k = 0; k < 9; k++) {
            float e = as2[srcs[k]] + ad2;
            e = e > 0.f ? e : 0.2f * e;
            e += mask[k];
            ek[k] = e; m = fmaxf(m, e);
        }
        float s = 0.f;
#pragma unroll
        for (int k = 0; k < 9; k++) { ek[k] = __expf(ek[k] - m); s += ek[k]; }
        float inv = 1.f / s;

        float acc2[8];
#pragma unroll
        for (int o = 0; o < 8; o++) acc2[o] = 0.f;
#pragma unroll
        for (int k = 0; k < 9; k++) {
            float w = ek[k] * inv;
            const float* hp = &h2s[srcs[k] * 9];
#pragma unroll
            for (int o = 0; o < 8; o++) acc2[o] += w * hp[o];
        }
        size_t base = (size_t)b * KPAD1 + n * 8;
#pragma unroll
        for (int o = 0; o < 8; o++) {
            float v = acc2[o] + __ldg(&b2[o]);
            __nv_bfloat16 hi = __float2bfloat16(v);
            g_flat_hi[base + o] = hi;
            g_flat_lo[base + o] = __float2bfloat16(v - __bfloat162float(hi));
        }
        if (n < 56) {
            __nv_bfloat16 z = __float2bfloat16(0.f);
            g_flat_hi[(size_t)b * KPAD1 + 1800 + n] = z;
            g_flat_lo[(size_t)b * KPAD1 + 1800 + n] = z;
        }
    }
}

// ---------------- HMMA GEMM: 128x128 tile, 8 warps (4M x 2N, m32n64 each) ----------
#define A_STR 80
#define B_STR 272
#define STG_SZ (128 * A_STR * 2 + 32 * B_STR * 2)      // 37888
#define OFF_AHI(s) ((s) * STG_SZ)
#define OFF_ALO(s) ((s) * STG_SZ + 128 * A_STR)
#define OFF_BHI(s) ((s) * STG_SZ + 128 * A_STR * 2)
#define OFF_BLO(s) ((s) * STG_SZ + 128 * A_STR * 2 + 32 * B_STR)
#define GEMM_SMEM (2 * STG_SZ)                          // 75776

__device__ __forceinline__ void ldm_x4(uint32_t* r, uint32_t addr) {
    asm volatile("ldmatrix.sync.aligned.m8n8.x4.shared.b16 {%0,%1,%2,%3}, [%4];"
                 : "=r"(r[0]), "=r"(r[1]), "=r"(r[2]), "=r"(r[3]) : "r"(addr));
}
__device__ __forceinline__ void ldm_x4t(uint32_t* r, uint32_t addr) {
    asm volatile("ldmatrix.sync.aligned.m8n8.x4.trans.shared.b16 {%0,%1,%2,%3}, [%4];"
                 : "=r"(r[0]), "=r"(r[1]), "=r"(r[2]), "=r"(r[3]) : "r"(addr));
}
__device__ __forceinline__ void mma16816(float* c, const uint32_t* a, uint32_t b0, uint32_t b1) {
    asm volatile("mma.sync.aligned.m16n8k16.row.col.f32.bf16.bf16.f32 "
                 "{%0,%1,%2,%3}, {%4,%5,%6,%7}, {%8,%9}, {%0,%1,%2,%3};"
                 : "+f"(c[0]), "+f"(c[1]), "+f"(c[2]), "+f"(c[3])
                 : "r"(a[0]), "r"(a[1]), "r"(a[2]), "r"(a[3]), "r"(b0), "r"(b1));
}

// FINAL=true: full K, add bias, write fp32 to Out (with N guard).
// FINAL=false: split-K partial (blockIdx.y), write fp32 to g_part, no bias.
template <bool FINAL>
__global__ void __launch_bounds__(256, 1) mma_gemm(
    const __nv_bfloat16* __restrict__ Ahi, const __nv_bfloat16* __restrict__ Alo, int lda,
    const float* __restrict__ B, int ldb, int Krows, int Ntot, int total_iters,
    const float* __restrict__ bias, float* __restrict__ Out) {
    extern __shared__ char smc[];
    uint32_t sb = smem_u32(smc);
    int t = threadIdx.x, wid = t >> 5, lane = t & 31;
    int n0 = blockIdx.x * 128;

    // split-K range
    int it_begin, it_count;
    {
        int sp = blockIdx.y, nsp = gridDim.y;
        int base = total_iters / nsp, rem = total_iters % nsp;
        it_count = base + (sp < rem ? 1 : 0);
        it_begin = sp * base + (sp < rem ? sp : rem);
    }

    // loader maps
    int arow = t >> 1, ahalf = t & 1;          // A: 128 rows x 2 halves (32B each)
    int brow = t >> 3, bg = t & 7;             // B: 32 rows x 8 col-groups (x4 strided)

    float acc[64];
#pragma unroll
    for (int c = 0; c < 64; c++) acc[c] = 0.f;

    uint4 pa_h[2], pa_l[2];
    float4 pb[4];

    auto load_regs = [&](int it_rel) {
        int k0 = (it_begin + it_rel) * 32;
        const char* gh = (const char*)(Ahi + (size_t)arow * lda + k0) + ahalf * 32;
        const char* gl = (const char*)(Alo + (size_t)arow * lda + k0) + ahalf * 32;
        pa_h[0] = *(const uint4*)gh;  pa_h[1] = *(const uint4*)(gh + 16);
        pa_l[0] = *(const uint4*)gl;  pa_l[1] = *(const uint4*)(gl + 16);
        int kg = k0 + brow;
        bool okk = kg < Krows;
        const float* brp = B + (size_t)kg * ldb + n0;
#pragma unroll
        for (int cc = 0; cc < 4; cc++) {
            int col = bg * 4 + cc * 32;
            bool ok = okk && (n0 + col < Ntot);
            pb[cc] = ok ? *(const float4*)(brp + col) : make_float4(0.f, 0.f, 0.f, 0.f);
        }
    };
    auto store_smem = [&](int s) {
        uint32_t ab = arow * A_STR + ahalf * 32;
        *(uint4*)(smc + OFF_AHI(s) + ab) = pa_h[0];
        *(uint4*)(smc + OFF_AHI(s) + ab + 16) = pa_h[1];
        *(uint4*)(smc + OFF_ALO(s) + ab) = pa_l[0];
        *(uint4*)(smc + OFF_ALO(s) + ab + 16) = pa_l[1];
#pragma unroll
        for (int cc = 0; cc < 4; cc++) {
            int col = bg * 4 + cc * 32;
            float4 v = pb[cc];
            union { __nv_bfloat16 h[4]; uint2 u; } uh, ul;
            uh.h[0] = __float2bfloat16(v.x); uh.h[1] = __float2bfloat16(v.y);
            uh.h[2] = __float2bfloat16(v.z); uh.h[3] = __float2bfloat16(v.w);
            ul.h[0] = __float2bfloat16(v.x - __bfloat162float(uh.h[0]));
            ul.h[1] = __float2bfloat16(v.y - __bfloat162float(uh.h[1]));
            ul.h[2] = __float2bfloat16(v.z - __bfloat162float(uh.h[2]));
            ul.h[3] = __float2bfloat16(v.w - __bfloat162float(uh.h[3]));
            *(uint2*)(smc + OFF_BHI(s) + brow * B_STR + col * 2) = uh.u;
            *(uint2*)(smc + OFF_BLO(s) + brow * B_STR + col * 2) = ul.u;
        }
    };

    load_regs(0);
    store_smem(0);
    __syncthreads();

    int wm = wid >> 1, wn = wid & 1;
    int m0 = wm * 32;
    int lrow = lane & 15, lsel = lane >> 4;

    for (int it = 0; it < it_count; it++) {
        int buf = it & 1;
        if (it + 1 < it_count) load_regs(it + 1);

        uint32_t aoff = (m0 + lrow) * A_STR + lsel * 16;
#pragma unroll
        for (int ks = 0; ks < 2; ks++) {
            uint32_t ah[2][4], al[2][4];
#pragma unroll
            for (int mh = 0; mh < 2; mh++) {
                ldm_x4(ah[mh], sb + OFF_AHI(buf) + aoff + mh * 16 * A_STR + ks * 32);
                ldm_x4(al[mh], sb + OFF_ALO(buf) + aoff + mh * 16 * A_STR + ks * 32);
            }
            uint32_t boff = (ks * 16 + lrow) * B_STR + wn * 128 + lsel * 16;
#pragma unroll
            for (int jj = 0; jj < 4; jj++) {
                uint32_t bh[4], bl[4];
                ldm_x4t(bh, sb + OFF_BHI(buf) + boff + jj * 32);
                ldm_x4t(bl, sb + OFF_BLO(buf) + boff + jj * 32);
#pragma unroll
                for (int mh = 0; mh < 2; mh++) {
                    float* c0 = acc + ((mh * 4 + jj) * 2 + 0) * 4;
                    float* c1 = acc + ((mh * 4 + jj) * 2 + 1) * 4;
                    mma16816(c0, ah[mh], bh[0], bh[1]);
                    mma16816(c1, ah[mh], bh[2], bh[3]);
                    mma16816(c0, ah[mh], bl[0], bl[1]);
                    mma16816(c1, ah[mh], bl[2], bl[3]);
                    mma16816(c0, al[mh], bh[0], bh[1]);
                    mma16816(c1, al[mh], bh[2], bh[3]);
                }
            }
        }

        if (it + 1 < it_count) store_smem(buf ^ 1);
        __syncthreads();
    }

    // ---------------- epilogue ----------------
    int g = lane >> 2, tg = lane & 3;
    float* dst = FINAL ? Out : (g_part + (size_t)blockIdx.y * BATCH * N1);
    int ldo = FINAL ? Ntot : N1;
#pragma unroll
    for (int mh = 0; mh < 2; mh++) {
#pragma unroll
        for (int jj = 0; jj < 4; jj++) {
#pragma unroll
            for (int nb = 0; nb < 2; nb++) {
                const float* a4 = acc + ((mh * 4 + jj) * 2 + nb) * 4;
                int col = n0 + wn * 64 + jj * 16 + nb * 8 + tg * 2;
                if (FINAL && col >= Ntot) continue;
                int m = wm * 32 + mh * 16 + g;
                float v0 = a4[0], v1 = a4[1], v2 = a4[2], v3 = a4[3];
                if (FINAL) {
                    float bs0 = __ldg(&bias[col]), bs1 = __ldg(&bias[col + 1]);
                    v0 += bs0; v1 += bs1; v2 += bs0; v3 += bs1;
                }
                *(float2*)(dst + (size_t)m * ldo + col) = make_float2(v0, v1);
                *(float2*)(dst + (size_t)(m + 8) * ldo + col) = make_float2(v2, v3);
            }
        }
    }
}

// ---------------- fc1 split-K reduce: sum + bias + relu -> bf16 hi/lo ----------------
__global__ void reduce_kernel(const float* __restrict__ b1) {
    int slot = blockIdx.x * 256 + threadIdx.x;        // 65536 float4 slots
    const float4* P = (const float4*)g_part;
    float4 v = P[slot];
#pragma unroll
    for (int s = 1; s < SPLITS; s++) {
        float4 u = P[(size_t)s * (BATCH * N1 / 4) + slot];
        v.x += u.x; v.y += u.y; v.z += u.z; v.w += u.w;
    }
    int base = slot * 4, col = base & (N1 - 1);
    v.x = fmaxf(v.x + __ldg(&b1[col]), 0.f);
    v.y = fmaxf(v.y + __ldg(&b1[col + 1]), 0.f);
    v.z = fmaxf(v.z + __ldg(&b1[col + 2]), 0.f);
    v.w = fmaxf(v.w + __ldg(&b1[col + 3]), 0.f);
    union { __nv_bfloat16 h[4]; uint2 u; } uh, ul;
    uh.h[0] = __float2bfloat16(v.x); uh.h[1] = __float2bfloat16(v.y);
    uh.h[2] = __float2bfloat16(v.z); uh.h[3] = __float2bfloat16(v.w);
    ul.h[0] = __float2bfloat16(v.x - __bfloat162float(uh.h[0]));
    ul.h[1] = __float2bfloat16(v.y - __bfloat162float(uh.h[1]));
    ul.h[2] = __float2bfloat16(v.z - __bfloat162float(uh.h[2]));
    ul.h[3] = __float2bfloat16(v.w - __bfloat162float(uh.h[3]));
    *(uint2*)(g_hid_hi + base) = uh.u;
    *(uint2*)(g_hid_lo + base) = ul.u;
}

// ---------------- launcher ----------------
extern "C" void kernel_launch(void* const* d_in, const int* in_sizes, int n_in,
                              void* d_out, int out_size) {
    const float* x4     = (const float*)d_in[0];
    const float* pool_w = (const float*)d_in[1];
    const float* pool_b = (const float*)d_in[2];
    const float* g1w    = (const float*)d_in[3];
    const float* g1as   = (const float*)d_in[4];
    const float* g1ad   = (const float*)d_in[5];
    const float* g1b    = (const float*)d_in[6];
    const float* g2w    = (const float*)d_in[7];
    const float* g2as   = (const float*)d_in[8];
    const float* g2ad   = (const float*)d_in[9];
    const float* g2b    = (const float*)d_in[10];
    const float* w1     = (const float*)d_in[11];
    const float* b1     = (const float*)d_in[12];
    const float* w2     = (const float*)d_in[13];
    const float* b2     = (const float*)d_in[14];
    float* out = (float*)d_out;

    const int gat_smem = (64 * NN + NN * 9 + NN * 5 + NN + 1024) * (int)sizeof(float);
    cudaFuncSetAttribute(gat_kernel, cudaFuncAttributeMaxDynamicSharedMemorySize, gat_smem);
    cudaFuncSetAttribute(mma_gemm<true>, cudaFuncAttributeMaxDynamicSharedMemorySize, GEMM_SMEM);
    cudaFuncSetAttribute(mma_gemm<false>, cudaFuncAttributeMaxDynamicSharedMemorySize, GEMM_SMEM);

    __nv_bfloat16 *fhi, *flo, *hhi, *hlo;
    cudaGetSymbolAddress((void**)&fhi, g_flat_hi);
    cudaGetSymbolAddress((void**)&flo, g_flat_lo);
    cudaGetSymbolAddress((void**)&hhi, g_hid_hi);
    cudaGetSymbolAddress((void**)&hlo, g_hid_lo);

    pool_kernel<<<dim3(128, 16), 225>>>(x4, pool_w);
    gat_kernel<<<128, 225, gat_smem>>>(pool_b, g1w, g1as, g1ad, g1b, g2w, g2as, g2ad, g2b);
    mma_gemm<false><<<dim3(N1 / 128, SPLITS), 256, GEMM_SMEM>>>(
        fhi, flo, KPAD1, w1, N1, 1800, N1, NITER1, nullptr, nullptr);
    reduce_kernel<<<BATCH * N1 / 1024, 256>>>(b1);
    mma_gemm<true><<<dim3((N2 + 127) / 128, 1), 256, GEMM_SMEM>>>(
        hhi, hlo, K2, w2, N2, K2, N2, NITER2, b2, out);
}

// round 5
// speedup vs baseline: 2.1847x; 1.0243x over previous
#include <cuda_runtime.h>
#include <cuda_bf16.h>
#include <cstdint>
#include <cstddef>

#define HG 9
#define WG 25
#define NN 225
#define BATCH 128
#define CIN 2048

#define KPAD1 1856   // 58 * 32
#define NITER1 58
#define K2 2048
#define NITER2 64
#define N1 2048
#define N2 20800
#define SPLITS 8

// ---------------- scratch ----------------
__device__ __align__(16) float g_fea_part[BATCH * 16 * NN * 8];
__device__ __align__(16) __nv_bfloat16 g_flat_hi[BATCH * KPAD1];
__device__ __align__(16) __nv_bfloat16 g_flat_lo[BATCH * KPAD1];
__device__ __align__(16) __nv_bfloat16 g_hid_hi[BATCH * K2];
__device__ __align__(16) __nv_bfloat16 g_hid_lo[BATCH * K2];
__device__ __align__(16) float g_part[SPLITS * BATCH * N1];   // fc1 split-K partials

__device__ __forceinline__ uint32_t smem_u32(const void* p) {
    uint32_t a;
    asm("{ .reg .u64 t; cvta.to.shared.u64 t, %1; cvt.u32.u64 %0, t; }" : "=r"(a) : "l"(p));
    return a;
}

// ---------------- kernel 1: pool (2048 -> 8) with packed f32x2 FMA ----------------
// grid (128, 16), block 225. Per block: 128 channels of one batch.
// Per thread-channel: 1 LDG.32 + 2 LDS.128 (broadcast) + 4 FFMA2 (was 8 FFMA).
__global__ void pool_kernel(const float* __restrict__ x4, const float* __restrict__ pw) {
    int b = blockIdx.x, cc = blockIdx.y, n = threadIdx.x;
    __shared__ unsigned long long s_w[128][4];   // [c][pair] packed (w_{2p}, w_{2p+1})
    for (int i = threadIdx.x; i < 512; i += blockDim.x) {
        int c = i >> 2, p = i & 3;
        float w0 = pw[(p * 2) * 2048 + cc * 128 + c];
        float w1 = pw[(p * 2 + 1) * 2048 + cc * 128 + c];
        unsigned long long u;
        asm("mov.b64 %0, {%1, %2};" : "=l"(u) : "f"(w0), "f"(w1));
        s_w[c][p] = u;
    }
    __syncthreads();

    const float* xp = x4 + ((size_t)(b * CIN + cc * 128)) * NN + n;
    unsigned long long a0 = 0ull, a1 = 0ull, a2 = 0ull, a3 = 0ull;  // (0.f,0.f) packed

#pragma unroll 16
    for (int c = 0; c < 128; c++) {
        float v = xp[(size_t)c * NN];
        unsigned long long vv;
        asm("mov.b64 %0, {%1, %1};" : "=l"(vv) : "f"(v));
        ulonglong2 wA = *(const ulonglong2*)&s_w[c][0];
        ulonglong2 wB = *(const ulonglong2*)&s_w[c][2];
        asm("fma.rn.f32x2 %0, %1, %2, %0;" : "+l"(a0) : "l"(vv), "l"(wA.x));
        asm("fma.rn.f32x2 %0, %1, %2, %0;" : "+l"(a1) : "l"(vv), "l"(wA.y));
        asm("fma.rn.f32x2 %0, %1, %2, %0;" : "+l"(a2) : "l"(vv), "l"(wB.x));
        asm("fma.rn.f32x2 %0, %1, %2, %0;" : "+l"(a3) : "l"(vv), "l"(wB.y));
    }
    unsigned long long* out =
        (unsigned long long*)(g_fea_part + ((size_t)((b * 16 + cc) * NN + n)) * 8);
    out[0] = a0; out[1] = a1; out[2] = a2; out[3] = a3;
}

// ---------------- kernel 2: fused GAT1 + GAT2 (unchanged) ----------------
__global__ void gat_kernel(const float* __restrict__ pb,
                           const float* __restrict__ W1, const float* __restrict__ a1s,
                           const float* __restrict__ a1d, const float* __restrict__ b1,
                           const float* __restrict__ W2, const float* __restrict__ a2s,
                           const float* __restrict__ a2d, const float* __restrict__ b2) {
    extern __shared__ float sm[];
    float* h1  = sm;               // [64][225]
    float* h2s = h1 + 64 * NN;     // [225][9]
    float* as1 = h2s + NN * 9;     // [225][5]
    float* as2 = as1 + NN * 5;     // [225]
    float* W1s = as2 + NN;         // 512
    float* W2s = W1s + 512;        // 512

    int b = blockIdx.x, n = threadIdx.x;
    for (int i = n; i < 512; i += blockDim.x) { W1s[i] = W1[i]; W2s[i] = W2[i]; }

    float fs[8];
#pragma unroll
    for (int k = 0; k < 8; k++) fs[k] = pb[k];
#pragma unroll
    for (int cc = 0; cc < 16; cc++) {
        const float* fp = g_fea_part + ((size_t)((b * 16 + cc) * NN + n)) * 8;
#pragma unroll
        for (int k = 0; k < 8; k++) fs[k] += fp[k];
    }
    __syncthreads();

    float ad1[4];
    {
        float as[4];
#pragma unroll
        for (int h = 0; h < 4; h++) { as[h] = 0.f; ad1[h] = 0.f; }
#pragma unroll
        for (int f = 0; f < 64; f++) {
            float hv = 0.f;
#pragma unroll
            for (int k = 0; k < 8; k++) hv += fs[k] * W1s[k * 64 + f];
            h1[f * NN + n] = hv;
            int hd = f >> 4;
            as[hd] += hv * __ldg(&a1s[f]);
            ad1[hd] += hv * __ldg(&a1d[f]);
        }
#pragma unroll
        for (int h = 0; h < 4; h++) as1[n * 5 + h] = as[h];
    }
    __syncthreads();

    int i = n / WG, j = n % WG;
    int srcs[9]; float mask[9];
#pragma unroll
    for (int k = 0; k < 9; k++) {
        int di = k / 3 - 1, dj = k % 3 - 1;
        int ni = i + di, nj = j + dj;
        bool v = (ni >= 0 && ni < HG && nj >= 0 && nj < WG);
        srcs[k] = v ? ni * WG + nj : n;
        mask[k] = v ? 0.f : -1e30f;
    }

    float h2[8];
#pragma unroll
    for (int o = 0; o < 8; o++) h2[o] = 0.f;

#pragma unroll
    for (int hd = 0; hd < 4; hd++) {
        float ek[9], m = -1e30f;
#pragma unroll
        for (int k = 0; k < 9; k++) {
            float e = as1[srcs[k] * 5 + hd] + ad1[hd];
            e = e > 0.f ? e : 0.2f * e;
            e += mask[k];
            ek[k] = e; m = fmaxf(m, e);
        }
        float s = 0.f;
#pragma unroll
        for (int k = 0; k < 9; k++) { ek[k] = __expf(ek[k] - m); s += ek[k]; }
        float inv = 1.f / s;

        float acc[16];
#pragma unroll
        for (int d = 0; d < 16; d++) acc[d] = 0.f;
#pragma unroll
        for (int k = 0; k < 9; k++) {
            float w = ek[k] * inv;
            const float* hp = &h1[(hd * 16) * NN + srcs[k]];
#pragma unroll
            for (int d = 0; d < 16; d++) acc[d] += w * hp[d * NN];
        }
#pragma unroll
        for (int d = 0; d < 16; d++) {
            int f = hd * 16 + d;
            float x1 = fmaxf(acc[d] + __ldg(&b1[f]), 0.f);
#pragma unroll
            for (int o = 0; o < 8; o++) h2[o] += x1 * W2s[f * 8 + o];
        }
    }

    float ad2 = 0.f;
    {
        float a = 0.f;
#pragma unroll
        for (int o = 0; o < 8; o++) {
            h2s[n * 9 + o] = h2[o];
            a   += h2[o] * __ldg(&a2s[o]);
            ad2 += h2[o] * __ldg(&a2d[o]);
        }
        as2[n] = a;
    }
    __syncthreads();

    {
        float ek[9], m = -1e30f;
#pragma unroll
        for (int k = 0; k < 9; k++) {
            float e = as2[srcs[k]] + ad2;
            e = e > 0.f ? e : 0.2f * e;
            e += mask[k];
            ek[k] = e; m = fmaxf(m, e);
        }
        float s = 0.f;
#pragma unroll
        for (int k = 0; k < 9; k++) { ek[k] = __expf(ek[k] - m); s += ek[k]; }
        float inv = 1.f / s;

        float acc2[8];
#pragma unroll
        for (int o = 0; o < 8; o++) acc2[o] = 0.f;
#pragma unroll
        for (int k = 0; k < 9; k++) {
            float w = ek[k] * inv;
            const float* hp = &h2s[srcs[k] * 9];
#pragma unroll
            for (int o = 0; o < 8; o++) acc2[o] += w * hp[o];
        }
        size_t base = (size_t)b * KPAD1 + n * 8;
#pragma unroll
        for (int o = 0; o < 8; o++) {
            float v = acc2[o] + __ldg(&b2[o]);
            __nv_bfloat16 hi = __float2bfloat16(v);
            g_flat_hi[base + o] = hi;
            g_flat_lo[base + o] = __float2bfloat16(v - __bfloat162float(hi));
        }
        if (n < 56) {
            __nv_bfloat16 z = __float2bfloat16(0.f);
            g_flat_hi[(size_t)b * KPAD1 + 1800 + n] = z;
            g_flat_lo[(size_t)b * KPAD1 + 1800 + n] = z;
        }
    }
}

// ---------------- HMMA GEMM: 128x128 tile, 8 warps (4M x 2N, m32n64 each) ----------
#define A_STR 80
#define B_STR 272
#define STG_SZ (128 * A_STR * 2 + 32 * B_STR * 2)      // 37888
#define OFF_AHI(s) ((s) * STG_SZ)
#define OFF_ALO(s) ((s) * STG_SZ + 128 * A_STR)
#define OFF_BHI(s) ((s) * STG_SZ + 128 * A_STR * 2)
#define OFF_BLO(s) ((s) * STG_SZ + 128 * A_STR * 2 + 32 * B_STR)
#define GEMM_SMEM (2 * STG_SZ)                          // 75776

__device__ __forceinline__ void ldm_x4(uint32_t* r, uint32_t addr) {
    asm volatile("ldmatrix.sync.aligned.m8n8.x4.shared.b16 {%0,%1,%2,%3}, [%4];"
                 : "=r"(r[0]), "=r"(r[1]), "=r"(r[2]), "=r"(r[3]) : "r"(addr));
}
__device__ __forceinline__ void ldm_x4t(uint32_t* r, uint32_t addr) {
    asm volatile("ldmatrix.sync.aligned.m8n8.x4.trans.shared.b16 {%0,%1,%2,%3}, [%4];"
                 : "=r"(r[0]), "=r"(r[1]), "=r"(r[2]), "=r"(r[3]) : "r"(addr));
}
__device__ __forceinline__ void mma16816(float* c, const uint32_t* a, uint32_t b0, uint32_t b1) {
    asm volatile("mma.sync.aligned.m16n8k16.row.col.f32.bf16.bf16.f32 "
                 "{%0,%1,%2,%3}, {%4,%5,%6,%7}, {%8,%9}, {%0,%1,%2,%3};"
                 : "+f"(c[0]), "+f"(c[1]), "+f"(c[2]), "+f"(c[3])
                 : "r"(a[0]), "r"(a[1]), "r"(a[2]), "r"(a[3]), "r"(b0), "r"(b1));
}

// FINAL=true: full K, add bias, write fp32 to Out (with N guard).
// FINAL=false: split-K partial (blockIdx.y), write fp32 to g_part, no bias.
template <bool FINAL>
__global__ void __launch_bounds__(256, 1) mma_gemm(
    const __nv_bfloat16* __restrict__ Ahi, const __nv_bfloat16* __restrict__ Alo, int lda,
    const float* __restrict__ B, int ldb, int Krows, int Ntot, int total_iters,
    const float* __restrict__ bias, float* __restrict__ Out) {
    extern __shared__ char smc[];
    uint32_t sb = smem_u32(smc);
    int t = threadIdx.x, wid = t >> 5, lane = t & 31;
    int n0 = blockIdx.x * 128;

    // split-K range
    int it_begin, it_count;
    {
        int sp = blockIdx.y, nsp = gridDim.y;
        int base = total_iters / nsp, rem = total_iters % nsp;
        it_count = base + (sp < rem ? 1 : 0);
        it_begin = sp * base + (sp < rem ? sp : rem);
    }

    // loader maps
    int arow = t >> 1, ahalf = t & 1;          // A: 128 rows x 2 halves (32B each)
    int brow = t >> 3, bg = t & 7;             // B: 32 rows x 8 col-groups (x4 strided)

    float acc[64];
#pragma unroll
    for (int c = 0; c < 64; c++) acc[c] = 0.f;

    uint4 pa_h[2], pa_l[2];
    float4 pb[4];

    auto load_regs = [&](int it_rel) {
        int k0 = (it_begin + it_rel) * 32;
        const char* gh = (const char*)(Ahi + (size_t)arow * lda + k0) + ahalf * 32;
        const char* gl = (const char*)(Alo + (size_t)arow * lda + k0) + ahalf * 32;
        pa_h[0] = *(const uint4*)gh;  pa_h[1] = *(const uint4*)(gh + 16);
        pa_l[0] = *(const uint4*)gl;  pa_l[1] = *(const uint4*)(gl + 16);
        int kg = k0 + brow;
        bool okk = kg < Krows;
        const float* brp = B + (size_t)kg * ldb + n0;
#pragma unroll
        for (int cc = 0; cc < 4; cc++) {
            int col = bg * 4 + cc * 32;
            bool ok = okk && (n0 + col < Ntot);
            pb[cc] = ok ? *(const float4*)(brp + col) : make_float4(0.f, 0.f, 0.f, 0.f);
        }
    };
    auto store_smem = [&](int s) {
        uint32_t ab = arow * A_STR + ahalf * 32;
        *(uint4*)(smc + OFF_AHI(s) + ab) = pa_h[0];
        *(uint4*)(smc + OFF_AHI(s) + ab + 16) = pa_h[1];
        *(uint4*)(smc + OFF_ALO(s) + ab) = pa_l[0];
        *(uint4*)(smc + OFF_ALO(s) + ab + 16) = pa_l[1];
#pragma unroll
        for (int cc = 0; cc < 4; cc++) {
            int col = bg * 4 + cc * 32;
            float4 v = pb[cc];
            union { __nv_bfloat16 h[4]; uint2 u; } uh, ul;
            uh.h[0] = __float2bfloat16(v.x); uh.h[1] = __float2bfloat16(v.y);
            uh.h[2] = __float2bfloat16(v.z); uh.h[3] = __float2bfloat16(v.w);
            ul.h[0] = __float2bfloat16(v.x - __bfloat162float(uh.h[0]));
            ul.h[1] = __float2bfloat16(v.y - __bfloat162float(uh.h[1]));
            ul.h[2] = __float2bfloat16(v.z - __bfloat162float(uh.h[2]));
            ul.h[3] = __float2bfloat16(v.w - __bfloat162float(uh.h[3]));
            *(uint2*)(smc + OFF_BHI(s) + brow * B_STR + col * 2) = uh.u;
            *(uint2*)(smc + OFF_BLO(s) + brow * B_STR + col * 2) = ul.u;
        }
    };

    load_regs(0);
    store_smem(0);
    __syncthreads();

    int wm = wid >> 1, wn = wid & 1;
    int m0 = wm * 32;
    int lrow = lane & 15, lsel = lane >> 4;

    for (int it = 0; it < it_count; it++) {
        int buf = it & 1;
        if (it + 1 < it_count) load_regs(it + 1);

        uint32_t aoff = (m0 + lrow) * A_STR + lsel * 16;
#pragma unroll
        for (int ks = 0; ks < 2; ks++) {
            uint32_t ah[2][4], al[2][4];
#pragma unroll
            for (int mh = 0; mh < 2; mh++) {
                ldm_x4(ah[mh], sb + OFF_AHI(buf) + aoff + mh * 16 * A_STR + ks * 32);
                ldm_x4(al[mh], sb + OFF_ALO(buf) + aoff + mh * 16 * A_STR + ks * 32);
            }
            uint32_t boff = (ks * 16 + lrow) * B_STR + wn * 128 + lsel * 16;
#pragma unroll
            for (int jj = 0; jj < 4; jj++) {
                uint32_t bh[4], bl[4];
                ldm_x4t(bh, sb + OFF_BHI(buf) + boff + jj * 32);
                ldm_x4t(bl, sb + OFF_BLO(buf) + boff + jj * 32);
#pragma unroll
                for (int mh = 0; mh < 2; mh++) {
                    float* c0 = acc + ((mh * 4 + jj) * 2 + 0) * 4;
                    float* c1 = acc + ((mh * 4 + jj) * 2 + 1) * 4;
                    mma16816(c0, ah[mh], bh[0], bh[1]);
                    mma16816(c1, ah[mh], bh[2], bh[3]);
                    mma16816(c0, ah[mh], bl[0], bl[1]);
                    mma16816(c1, ah[mh], bl[2], bl[3]);
                    mma16816(c0, al[mh], bh[0], bh[1]);
                    mma16816(c1, al[mh], bh[2], bh[3]);
                }
            }
        }

        if (it + 1 < it_count) store_smem(buf ^ 1);
        __syncthreads();
    }

    // ---------------- epilogue ----------------
    int g = lane >> 2, tg = lane & 3;
    float* dst = FINAL ? Out : (g_part + (size_t)blockIdx.y * BATCH * N1);
    int ldo = FINAL ? Ntot : N1;
#pragma unroll
    for (int mh = 0; mh < 2; mh++) {
#pragma unroll
        for (int jj = 0; jj < 4; jj++) {
#pragma unroll
            for (int nb = 0; nb < 2; nb++) {
                const float* a4 = acc + ((mh * 4 + jj) * 2 + nb) * 4;
                int col = n0 + wn * 64 + jj * 16 + nb * 8 + tg * 2;
                if (FINAL && col >= Ntot) continue;
                int m = wm * 32 + mh * 16 + g;
                float v0 = a4[0], v1 = a4[1], v2 = a4[2], v3 = a4[3];
                if (FINAL) {
                    float bs0 = __ldg(&bias[col]), bs1 = __ldg(&bias[col + 1]);
                    v0 += bs0; v1 += bs1; v2 += bs0; v3 += bs1;
                }
                *(float2*)(dst + (size_t)m * ldo + col) = make_float2(v0, v1);
                *(float2*)(dst + (size_t)(m + 8) * ldo + col) = make_float2(v2, v3);
            }
        }
    }
}

// ---------------- fc1 split-K reduce: sum + bias + relu -> bf16 hi/lo ----------------
__global__ void reduce_kernel(const float* __restrict__ b1) {
    int slot = blockIdx.x * 256 + threadIdx.x;        // 65536 float4 slots
    const float4* P = (const float4*)g_part;
    float4 v = P[slot];
#pragma unroll
    for (int s = 1; s < SPLITS; s++) {
        float4 u = P[(size_t)s * (BATCH * N1 / 4) + slot];
        v.x += u.x; v.y += u.y; v.z += u.z; v.w += u.w;
    }
    int base = slot * 4, col = base & (N1 - 1);
    v.x = fmaxf(v.x + __ldg(&b1[col]), 0.f);
    v.y = fmaxf(v.y + __ldg(&b1[col + 1]), 0.f);
    v.z = fmaxf(v.z + __ldg(&b1[col + 2]), 0.f);
    v.w = fmaxf(v.w + __ldg(&b1[col + 3]), 0.f);
    union { __nv_bfloat16 h[4]; uint2 u; } uh, ul;
    uh.h[0] = __float2bfloat16(v.x); uh.h[1] = __float2bfloat16(v.y);
    uh.h[2] = __float2bfloat16(v.z); uh.h[3] = __float2bfloat16(v.w);
    ul.h[0] = __float2bfloat16(v.x - __bfloat162float(uh.h[0]));
    ul.h[1] = __float2bfloat16(v.y - __bfloat162float(uh.h[1]));
    ul.h[2] = __float2bfloat16(v.z - __bfloat162float(uh.h[2]));
    ul.h[3] = __float2bfloat16(v.w - __bfloat162float(uh.h[3]));
    *(uint2*)(g_hid_hi + base) = uh.u;
    *(uint2*)(g_hid_lo + base) = ul.u;
}

// ---------------- launcher ----------------
extern "C" void kernel_launch(void* const* d_in, const int* in_sizes, int n_in,
                              void* d_out, int out_size) {
    const float* x4     = (const float*)d_in[0];
    const float* pool_w = (const float*)d_in[1];
    const float* pool_b = (const float*)d_in[2];
    const float* g1w    = (const float*)d_in[3];
    const float* g1as   = (const float*)d_in[4];
    const float* g1ad   = (const float*)d_in[5];
    const float* g1b    = (const float*)d_in[6];
    const float* g2w    = (const float*)d_in[7];
    const float* g2as   = (const float*)d_in[8];
    const float* g2ad   = (const float*)d_in[9];
    const float* g2b    = (const float*)d_in[10];
    const float* w1     = (const float*)d_in[11];
    const float* b1     = (const float*)d_in[12];
    const float* w2     = (const float*)d_in[13];
    const float* b2     = (const float*)d_in[14];
    float* out = (float*)d_out;

    const int gat_smem = (64 * NN + NN * 9 + NN * 5 + NN + 1024) * (int)sizeof(float);
    cudaFuncSetAttribute(gat_kernel, cudaFuncAttributeMaxDynamicSharedMemorySize, gat_smem);
    cudaFuncSetAttribute(mma_gemm<true>, cudaFuncAttributeMaxDynamicSharedMemorySize, GEMM_SMEM);
    cudaFuncSetAttribute(mma_gemm<false>, cudaFuncAttributeMaxDynamicSharedMemorySize, GEMM_SMEM);

    __nv_bfloat16 *fhi, *flo, *hhi, *hlo;
    cudaGetSymbolAddress((void**)&fhi, g_flat_hi);
    cudaGetSymbolAddress((void**)&flo, g_flat_lo);
    cudaGetSymbolAddress((void**)&hhi, g_hid_hi);
    cudaGetSymbolAddress((void**)&hlo, g_hid_lo);

    pool_kernel<<<dim3(128, 16), 225>>>(x4, pool_w);
    gat_kernel<<<128, 225, gat_smem>>>(pool_b, g1w, g1as, g1ad, g1b, g2w, g2as, g2ad, g2b);
    mma_gemm<false><<<dim3(N1 / 128, SPLITS), 256, GEMM_SMEM>>>(
        fhi, flo, KPAD1, w1, N1, 1800, N1, NITER1, nullptr, nullptr);
    reduce_kernel<<<BATCH * N1 / 1024, 256>>>(b1);
    mma_gemm<true><<<dim3((N2 + 127) / 128, 1), 256, GEMM_SMEM>>>(
        hhi, hlo, K2, w2, N2, K2, N2, NITER2, b2, out);
}

// round 6
// speedup vs baseline: 2.3099x; 1.0573x over previous
#include <cuda_runtime.h>
#include <cuda_bf16.h>
#include <cstdint>
#include <cstddef>

#define HG 9
#define WG 25
#define NN 225
#define BATCH 128
#define CIN 2048

#define KPAD1 1856   // 58 * 32
#define NITER1 58
#define K2 2048
#define NITER2 64
#define N1 2048
#define N2 20800
#define SPLITS1 8
#define SPLITS2 2

// ---------------- scratch ----------------
__device__ __align__(16) float g_fea_part[BATCH * 16 * NN * 8];
__device__ __align__(16) __nv_bfloat16 g_flat_hi[BATCH * KPAD1];
__device__ __align__(16) __nv_bfloat16 g_flat_lo[BATCH * KPAD1];
__device__ __align__(16) __nv_bfloat16 g_hid_hi[BATCH * K2];
__device__ __align__(16) __nv_bfloat16 g_hid_lo[BATCH * K2];
__device__ __align__(16) float g_part[SPLITS1 * BATCH * N1];   // fc1 partials
__device__ __align__(16) float g_part2[SPLITS2 * BATCH * N2];  // fc2 partials

__device__ __forceinline__ uint32_t smem_u32(const void* p) {
    uint32_t a;
    asm("{ .reg .u64 t; cvta.to.shared.u64 t, %1; cvt.u32.u64 %0, t; }" : "=r"(a) : "l"(p));
    return a;
}

// ---------------- kernel 1: pool (2048 -> 8) packed f32x2 FMA (frozen) ----------------
__global__ void pool_kernel(const float* __restrict__ x4, const float* __restrict__ pw) {
    int b = blockIdx.x, cc = blockIdx.y, n = threadIdx.x;
    __shared__ unsigned long long s_w[128][4];
    for (int i = threadIdx.x; i < 512; i += blockDim.x) {
        int c = i >> 2, p = i & 3;
        float w0 = pw[(p * 2) * 2048 + cc * 128 + c];
        float w1 = pw[(p * 2 + 1) * 2048 + cc * 128 + c];
        unsigned long long u;
        asm("mov.b64 %0, {%1, %2};" : "=l"(u) : "f"(w0), "f"(w1));
        s_w[c][p] = u;
    }
    __syncthreads();

    const float* xp = x4 + ((size_t)(b * CIN + cc * 128)) * NN + n;
    unsigned long long a0 = 0ull, a1 = 0ull, a2 = 0ull, a3 = 0ull;

#pragma unroll 16
    for (int c = 0; c < 128; c++) {
        float v = xp[(size_t)c * NN];
        unsigned long long vv;
        asm("mov.b64 %0, {%1, %1};" : "=l"(vv) : "f"(v));
        ulonglong2 wA = *(const ulonglong2*)&s_w[c][0];
        ulonglong2 wB = *(const ulonglong2*)&s_w[c][2];
        asm("fma.rn.f32x2 %0, %1, %2, %0;" : "+l"(a0) : "l"(vv), "l"(wA.x));
        asm("fma.rn.f32x2 %0, %1, %2, %0;" : "+l"(a1) : "l"(vv), "l"(wA.y));
        asm("fma.rn.f32x2 %0, %1, %2, %0;" : "+l"(a2) : "l"(vv), "l"(wB.x));
        asm("fma.rn.f32x2 %0, %1, %2, %0;" : "+l"(a3) : "l"(vv), "l"(wB.y));
    }
    unsigned long long* out =
        (unsigned long long*)(g_fea_part + ((size_t)((b * 16 + cc) * NN + n)) * 8);
    out[0] = a0; out[1] = a1; out[2] = a2; out[3] = a3;
}

// ---------------- kernel 2: fused GAT1 + GAT2 (frozen) ----------------
__global__ void gat_kernel(const float* __restrict__ pb,
                           const float* __restrict__ W1, const float* __restrict__ a1s,
                           const float* __restrict__ a1d, const float* __restrict__ b1,
                           const float* __restrict__ W2, const float* __restrict__ a2s,
                           const float* __restrict__ a2d, const float* __restrict__ b2) {
    extern __shared__ float sm[];
    float* h1  = sm;
    float* h2s = h1 + 64 * NN;
    float* as1 = h2s + NN * 9;
    float* as2 = as1 + NN * 5;
    float* W1s = as2 + NN;
    float* W2s = W1s + 512;

    int b = blockIdx.x, n = threadIdx.x;
    for (int i = n; i < 512; i += blockDim.x) { W1s[i] = W1[i]; W2s[i] = W2[i]; }

    float fs[8];
#pragma unroll
    for (int k = 0; k < 8; k++) fs[k] = pb[k];
#pragma unroll
    for (int cc = 0; cc < 16; cc++) {
        const float* fp = g_fea_part + ((size_t)((b * 16 + cc) * NN + n)) * 8;
#pragma unroll
        for (int k = 0; k < 8; k++) fs[k] += fp[k];
    }
    __syncthreads();

    float ad1[4];
    {
        float as[4];
#pragma unroll
        for (int h = 0; h < 4; h++) { as[h] = 0.f; ad1[h] = 0.f; }
#pragma unroll
        for (int f = 0; f < 64; f++) {
            float hv = 0.f;
#pragma unroll
            for (int k = 0; k < 8; k++) hv += fs[k] * W1s[k * 64 + f];
            h1[f * NN + n] = hv;
            int hd = f >> 4;
            as[hd] += hv * __ldg(&a1s[f]);
            ad1[hd] += hv * __ldg(&a1d[f]);
        }
#pragma unroll
        for (int h = 0; h < 4; h++) as1[n * 5 + h] = as[h];
    }
    __syncthreads();

    int i = n / WG, j = n % WG;
    int srcs[9]; float mask[9];
#pragma unroll
    for (int k = 0; k < 9; k++) {
        int di = k / 3 - 1, dj = k % 3 - 1;
        int ni = i + di, nj = j + dj;
        bool v = (ni >= 0 && ni < HG && nj >= 0 && nj < WG);
        srcs[k] = v ? ni * WG + nj : n;
        mask[k] = v ? 0.f : -1e30f;
    }

    float h2[8];
#pragma unroll
    for (int o = 0; o < 8; o++) h2[o] = 0.f;

#pragma unroll
    for (int hd = 0; hd < 4; hd++) {
        float ek[9], m = -1e30f;
#pragma unroll
        for (int k = 0; k < 9; k++) {
            float e = as1[srcs[k] * 5 + hd] + ad1[hd];
            e = e > 0.f ? e : 0.2f * e;
            e += mask[k];
            ek[k] = e; m = fmaxf(m, e);
        }
        float s = 0.f;
#pragma unroll
        for (int k = 0; k < 9; k++) { ek[k] = __expf(ek[k] - m); s += ek[k]; }
        float inv = 1.f / s;

        float acc[16];
#pragma unroll
        for (int d = 0; d < 16; d++) acc[d] = 0.f;
#pragma unroll
        for (int k = 0; k < 9; k++) {
            float w = ek[k] * inv;
            const float* hp = &h1[(hd * 16) * NN + srcs[k]];
#pragma unroll
            for (int d = 0; d < 16; d++) acc[d] += w * hp[d * NN];
        }
#pragma unroll
        for (int d = 0; d < 16; d++) {
            int f = hd * 16 + d;
            float x1 = fmaxf(acc[d] + __ldg(&b1[f]), 0.f);
#pragma unroll
            for (int o = 0; o < 8; o++) h2[o] += x1 * W2s[f * 8 + o];
        }
    }

    float ad2 = 0.f;
    {
        float a = 0.f;
#pragma unroll
        for (int o = 0; o < 8; o++) {
            h2s[n * 9 + o] = h2[o];
            a   += h2[o] * __ldg(&a2s[o]);
            ad2 += h2[o] * __ldg(&a2d[o]);
        }
        as2[n] = a;
    }
    __syncthreads();

    {
        float ek[9], m = -1e30f;
#pragma unroll
        for (int k = 0; k < 9; k++) {
            float e = as2[srcs[k]] + ad2;
            e = e > 0.f ? e : 0.2f * e;
            e += mask[k];
            ek[k] = e; m = fmaxf(m, e);
        }
        float s = 0.f;
#pragma unroll
        for (int k = 0; k < 9; k++) { ek[k] = __expf(ek[k] - m); s += ek[k]; }
        float inv = 1.f / s;

        float acc2[8];
#pragma unroll
        for (int o = 0; o < 8; o++) acc2[o] = 0.f;
#pragma unroll
        for (int k = 0; k < 9; k++) {
            float w = ek[k] * inv;
            const float* hp = &h2s[srcs[k] * 9];
#pragma unroll
            for (int o = 0; o < 8; o++) acc2[o] += w * hp[o];
        }
        size_t base = (size_t)b * KPAD1 + n * 8;
#pragma unroll
        for (int o = 0; o < 8; o++) {
            float v = acc2[o] + __ldg(&b2[o]);
            __nv_bfloat16 hi = __float2bfloat16(v);
            g_flat_hi[base + o] = hi;
            g_flat_lo[base + o] = __float2bfloat16(v - __bfloat162float(hi));
        }
        if (n < 56) {
            __nv_bfloat16 z = __float2bfloat16(0.f);
            g_flat_hi[(size_t)b * KPAD1 + 1800 + n] = z;
            g_flat_lo[(size_t)b * KPAD1 + 1800 + n] = z;
        }
    }
}

// ---------------- HMMA GEMM (always split-K partial) ----------------
// 128x128 tile, 8 warps (4M x 2N), BK=32. 4-chain interleaved MMAs + B-frag pipeline.
#define A_STR 80
#define B_STR 272
#define STG_SZ (128 * A_STR * 2 + 32 * B_STR * 2)      // 37888
#define OFF_AHI(s) ((s) * STG_SZ)
#define OFF_ALO(s) ((s) * STG_SZ + 128 * A_STR)
#define OFF_BHI(s) ((s) * STG_SZ + 128 * A_STR * 2)
#define OFF_BLO(s) ((s) * STG_SZ + 128 * A_STR * 2 + 32 * B_STR)
#define GEMM_SMEM (2 * STG_SZ)                          // 75776

__device__ __forceinline__ void ldm_x4(uint32_t* r, uint32_t addr) {
    asm volatile("ldmatrix.sync.aligned.m8n8.x4.shared.b16 {%0,%1,%2,%3}, [%4];"
                 : "=r"(r[0]), "=r"(r[1]), "=r"(r[2]), "=r"(r[3]) : "r"(addr));
}
__device__ __forceinline__ void ldm_x4t(uint32_t* r, uint32_t addr) {
    asm volatile("ldmatrix.sync.aligned.m8n8.x4.trans.shared.b16 {%0,%1,%2,%3}, [%4];"
                 : "=r"(r[0]), "=r"(r[1]), "=r"(r[2]), "=r"(r[3]) : "r"(addr));
}
__device__ __forceinline__ void mma16816(float* c, const uint32_t* a, uint32_t b0, uint32_t b1) {
    asm volatile("mma.sync.aligned.m16n8k16.row.col.f32.bf16.bf16.f32 "
                 "{%0,%1,%2,%3}, {%4,%5,%6,%7}, {%8,%9}, {%0,%1,%2,%3};"
                 : "+f"(c[0]), "+f"(c[1]), "+f"(c[2]), "+f"(c[3])
                 : "r"(a[0]), "r"(a[1]), "r"(a[2]), "r"(a[3]), "r"(b0), "r"(b1));
}

__global__ void __launch_bounds__(256, 2) mma_gemm(
    const __nv_bfloat16* __restrict__ Ahi, const __nv_bfloat16* __restrict__ Alo, int lda,
    const float* __restrict__ B, int ldb, int Krows, int Ntot, int total_iters,
    float* __restrict__ part) {
    extern __shared__ char smc[];
    uint32_t sb = smem_u32(smc);
    int t = threadIdx.x, wid = t >> 5, lane = t & 31;
    int n0 = blockIdx.x * 128;

    int it_begin, it_count;
    {
        int sp = blockIdx.y, nsp = gridDim.y;
        int base = total_iters / nsp, rem = total_iters % nsp;
        it_count = base + (sp < rem ? 1 : 0);
        it_begin = sp * base + (sp < rem ? sp : rem);
    }

    int arow = t >> 1, ahalf = t & 1;
    int brow = t >> 3, bg = t & 7;

    float acc[64];
#pragma unroll
    for (int c = 0; c < 64; c++) acc[c] = 0.f;

    uint4 pa_h[2], pa_l[2];
    float4 pb[4];

    auto load_regs = [&](int it_rel) {
        int k0 = (it_begin + it_rel) * 32;
        const char* gh = (const char*)(Ahi + (size_t)arow * lda + k0) + ahalf * 32;
        const char* gl = (const char*)(Alo + (size_t)arow * lda + k0) + ahalf * 32;
        pa_h[0] = *(const uint4*)gh;  pa_h[1] = *(const uint4*)(gh + 16);
        pa_l[0] = *(const uint4*)gl;  pa_l[1] = *(const uint4*)(gl + 16);
        int kg = k0 + brow;
        bool okk = kg < Krows;
        const float* brp = B + (size_t)kg * ldb + n0;
#pragma unroll
        for (int cc = 0; cc < 4; cc++) {
            int col = bg * 4 + cc * 32;
            bool ok = okk && (n0 + col < Ntot);
            pb[cc] = ok ? *(const float4*)(brp + col) : make_float4(0.f, 0.f, 0.f, 0.f);
        }
    };
    auto store_smem = [&](int s) {
        uint32_t ab = arow * A_STR + ahalf * 32;
        *(uint4*)(smc + OFF_AHI(s) + ab) = pa_h[0];
        *(uint4*)(smc + OFF_AHI(s) + ab + 16) = pa_h[1];
        *(uint4*)(smc + OFF_ALO(s) + ab) = pa_l[0];
        *(uint4*)(smc + OFF_ALO(s) + ab + 16) = pa_l[1];
#pragma unroll
        for (int cc = 0; cc < 4; cc++) {
            int col = bg * 4 + cc * 32;
            float4 v = pb[cc];
            union { __nv_bfloat16 h[4]; uint2 u; } uh, ul;
            uh.h[0] = __float2bfloat16(v.x); uh.h[1] = __float2bfloat16(v.y);
            uh.h[2] = __float2bfloat16(v.z); uh.h[3] = __float2bfloat16(v.w);
            ul.h[0] = __float2bfloat16(v.x - __bfloat162float(uh.h[0]));
            ul.h[1] = __float2bfloat16(v.y - __bfloat162float(uh.h[1]));
            ul.h[2] = __float2bfloat16(v.z - __bfloat162float(uh.h[2]));
            ul.h[3] = __float2bfloat16(v.w - __bfloat162float(uh.h[3]));
            *(uint2*)(smc + OFF_BHI(s) + brow * B_STR + col * 2) = uh.u;
            *(uint2*)(smc + OFF_BLO(s) + brow * B_STR + col * 2) = ul.u;
        }
    };

    load_regs(0);
    store_smem(0);
    __syncthreads();

    int wm = wid >> 1, wn = wid & 1;
    int m0 = wm * 32;
    int lrow = lane & 15, lsel = lane >> 4;

    for (int it = 0; it < it_count; it++) {
        int buf = it & 1;
        if (it + 1 < it_count) load_regs(it + 1);

        uint32_t aoff = (m0 + lrow) * A_STR + lsel * 16;
#pragma unroll
        for (int ks = 0; ks < 2; ks++) {
            uint32_t ah[2][4], al[2][4];
#pragma unroll
            for (int mh = 0; mh < 2; mh++) {
                ldm_x4(ah[mh], sb + OFF_AHI(buf) + aoff + mh * 16 * A_STR + ks * 32);
                ldm_x4(al[mh], sb + OFF_ALO(buf) + aoff + mh * 16 * A_STR + ks * 32);
            }
            uint32_t boff = (ks * 16 + lrow) * B_STR + wn * 128 + lsel * 16;

            uint32_t bfh[2][4], bfl[2][4];
            ldm_x4t(bfh[0], sb + OFF_BHI(buf) + boff);
            ldm_x4t(bfl[0], sb + OFF_BLO(buf) + boff);
#pragma unroll
            for (int jj = 0; jj < 4; jj++) {
                int cur = jj & 1;
                if (jj < 3) {   // prefetch next B fragments: latency hidden behind 12 MMAs
                    ldm_x4t(bfh[cur ^ 1], sb + OFF_BHI(buf) + boff + (jj + 1) * 32);
                    ldm_x4t(bfl[cur ^ 1], sb + OFF_BLO(buf) + boff + (jj + 1) * 32);
                }
                const uint32_t* bh = bfh[cur];
                const uint32_t* bl = bfl[cur];
                float* c00 = acc + ((0 * 4 + jj) * 2 + 0) * 4;
                float* c01 = acc + ((0 * 4 + jj) * 2 + 1) * 4;
                float* c10 = acc + ((1 * 4 + jj) * 2 + 0) * 4;
                float* c11 = acc + ((1 * 4 + jj) * 2 + 1) * 4;
                // 4 independent accumulate chains, round-robin -> no RAW stall
                mma16816(c00, ah[0], bh[0], bh[1]);
                mma16816(c01, ah[0], bh[2], bh[3]);
                mma16816(c10, ah[1], bh[0], bh[1]);
                mma16816(c11, ah[1], bh[2], bh[3]);
                mma16816(c00, ah[0], bl[0], bl[1]);
                mma16816(c01, ah[0], bl[2], bl[3]);
                mma16816(c10, ah[1], bl[0], bl[1]);
                mma16816(c11, ah[1], bl[2], bl[3]);
                mma16816(c00, al[0], bh[0], bh[1]);
                mma16816(c01, al[0], bh[2], bh[3]);
                mma16816(c10, al[1], bh[0], bh[1]);
                mma16816(c11, al[1], bh[2], bh[3]);
            }
        }

        if (it + 1 < it_count) store_smem(buf ^ 1);
        __syncthreads();
    }

    // epilogue: fp32 partial to part[split][128][Ntot]
    int g = lane >> 2, tg = lane & 3;
    float* dst = part + (size_t)blockIdx.y * BATCH * (size_t)Ntot;
#pragma unroll
    for (int mh = 0; mh < 2; mh++) {
#pragma unroll
        for (int jj = 0; jj < 4; jj++) {
#pragma unroll
            for (int nb = 0; nb < 2; nb++) {
                const float* a4 = acc + ((mh * 4 + jj) * 2 + nb) * 4;
                int col = n0 + wn * 64 + jj * 16 + nb * 8 + tg * 2;
                if (col >= Ntot) continue;
                int m = wm * 32 + mh * 16 + g;
                *(float2*)(dst + (size_t)m * Ntot + col) = make_float2(a4[0], a4[1]);
                *(float2*)(dst + (size_t)(m + 8) * Ntot + col) = make_float2(a4[2], a4[3]);
            }
        }
    }
}

// ---------------- fc1 reduce: 8 partials + bias + relu -> bf16 hi/lo ----------------
__global__ void reduce_kernel(const float* __restrict__ b1) {
    int slot = blockIdx.x * 256 + threadIdx.x;
    const float4* P = (const float4*)g_part;
    float4 v = P[slot];
#pragma unroll
    for (int s = 1; s < SPLITS1; s++) {
        float4 u = P[(size_t)s * (BATCH * N1 / 4) + slot];
        v.x += u.x; v.y += u.y; v.z += u.z; v.w += u.w;
    }
    int base = slot * 4, col = base & (N1 - 1);
    v.x = fmaxf(v.x + __ldg(&b1[col]), 0.f);
    v.y = fmaxf(v.y + __ldg(&b1[col + 1]), 0.f);
    v.z = fmaxf(v.z + __ldg(&b1[col + 2]), 0.f);
    v.w = fmaxf(v.w + __ldg(&b1[col + 3]), 0.f);
    union { __nv_bfloat16 h[4]; uint2 u; } uh, ul;
    uh.h[0] = __float2bfloat16(v.x); uh.h[1] = __float2bfloat16(v.y);
    uh.h[2] = __float2bfloat16(v.z); uh.h[3] = __float2bfloat16(v.w);
    ul.h[0] = __float2bfloat16(v.x - __bfloat162float(uh.h[0]));
    ul.h[1] = __float2bfloat16(v.y - __bfloat162float(uh.h[1]));
    ul.h[2] = __float2bfloat16(v.z - __bfloat162float(uh.h[2]));
    ul.h[3] = __float2bfloat16(v.w - __bfloat162float(uh.h[3]));
    *(uint2*)(g_hid_hi + base) = uh.u;
    *(uint2*)(g_hid_lo + base) = ul.u;
}

// ---------------- fc2 reduce: 2 partials + bias -> fp32 out ----------------
__global__ void reduce2_kernel(const float* __restrict__ b2, float* __restrict__ out) {
    int slot = blockIdx.x * 256 + threadIdx.x;     // 665600 float4 slots
    const float4* P = (const float4*)g_part2;
    float4 v = P[slot];
    float4 u = P[(size_t)(BATCH * N2 / 4) + slot];
    v.x += u.x; v.y += u.y; v.z += u.z; v.w += u.w;
    int base = slot * 4;
    int col = base % N2;
    v.x += __ldg(&b2[col]);
    v.y += __ldg(&b2[col + 1]);
    v.z += __ldg(&b2[col + 2]);
    v.w += __ldg(&b2[col + 3]);
    *(float4*)(out + base) = v;
}

// ---------------- launcher ----------------
extern "C" void kernel_launch(void* const* d_in, const int* in_sizes, int n_in,
                              void* d_out, int out_size) {
    const float* x4     = (const float*)d_in[0];
    const float* pool_w = (const float*)d_in[1];
    const float* pool_b = (const float*)d_in[2];
    const float* g1w    = (const float*)d_in[3];
    const float* g1as   = (const float*)d_in[4];
    const float* g1ad   = (const float*)d_in[5];
    const float* g1b    = (const float*)d_in[6];
    const float* g2w    = (const float*)d_in[7];
    const float* g2as   = (const float*)d_in[8];
    const float* g2ad   = (const float*)d_in[9];
    const float* g2b    = (const float*)d_in[10];
    const float* w1     = (const float*)d_in[11];
    const float* b1     = (const float*)d_in[12];
    const float* w2     = (const float*)d_in[13];
    const float* b2     = (const float*)d_in[14];
    float* out = (float*)d_out;

    const int gat_smem = (64 * NN + NN * 9 + NN * 5 + NN + 1024) * (int)sizeof(float);
    cudaFuncSetAttribute(gat_kernel, cudaFuncAttributeMaxDynamicSharedMemorySize, gat_smem);
    cudaFuncSetAttribute(mma_gemm, cudaFuncAttributeMaxDynamicSharedMemorySize, GEMM_SMEM);

    __nv_bfloat16 *fhi, *flo, *hhi, *hlo;
    float *p1, *p2;
    cudaGetSymbolAddress((void**)&fhi, g_flat_hi);
    cudaGetSymbolAddress((void**)&flo, g_flat_lo);
    cudaGetSymbolAddress((void**)&hhi, g_hid_hi);
    cudaGetSymbolAddress((void**)&hlo, g_hid_lo);
    cudaGetSymbolAddress((void**)&p1, g_part);
    cudaGetSymbolAddress((void**)&p2, g_part2);

    pool_kernel<<<dim3(128, 16), 225>>>(x4, pool_w);
    gat_kernel<<<128, 225, gat_smem>>>(pool_b, g1w, g1as, g1ad, g1b, g2w, g2as, g2ad, g2b);
    mma_gemm<<<dim3(N1 / 128, SPLITS1), 256, GEMM_SMEM>>>(
        fhi, flo, KPAD1, w1, N1, 1800, N1, NITER1, p1);
    reduce_kernel<<<BATCH * N1 / 1024, 256>>>(b1);
    mma_gemm<<<dim3((N2 + 127) / 128, SPLITS2), 256, GEMM_SMEM>>>(
        hhi, hlo, K2, w2, N2, K2, N2, NITER2, p2);
    reduce2_kernel<<<BATCH * N2 / 1024, 256>>>(b2, out);
}

// round 7
// speedup vs baseline: 3.4984x; 1.5146x over previous
#include <cuda_runtime.h>
#include <cuda_fp16.h>
#include <cstdint>
#include <cstddef>

#define HG 9
#define WG 25
#define NN 225
#define BATCH 128
#define CIN 2048

#define KPAD1 1856   // 58 * 32
#define NITER1 58
#define K2 2048
#define NITER2 64
#define N1 2048
#define N2 20800
#define SPLITS1 8
#define SPLITS2 2

// ---------------- scratch ----------------
__device__ __align__(16) float g_fea_part[BATCH * 16 * NN * 8];
__device__ __align__(16) __half g_flat_h[BATCH * KPAD1];
__device__ __align__(16) __half g_hid_h[BATCH * K2];
__device__ __align__(16) float g_part[SPLITS1 * BATCH * N1];   // fc1 partials
__device__ __align__(16) float g_part2[SPLITS2 * BATCH * N2];  // fc2 partials

__device__ __forceinline__ uint32_t smem_u32(const void* p) {
    uint32_t a;
    asm("{ .reg .u64 t; cvta.to.shared.u64 t, %1; cvt.u32.u64 %0, t; }" : "=r"(a) : "l"(p));
    return a;
}

// ---------------- kernel 1: pool (2048 -> 8) packed f32x2 FMA (frozen) ----------------
__global__ void pool_kernel(const float* __restrict__ x4, const float* __restrict__ pw) {
    int b = blockIdx.x, cc = blockIdx.y, n = threadIdx.x;
    __shared__ unsigned long long s_w[128][4];
    for (int i = threadIdx.x; i < 512; i += blockDim.x) {
        int c = i >> 2, p = i & 3;
        float w0 = pw[(p * 2) * 2048 + cc * 128 + c];
        float w1 = pw[(p * 2 + 1) * 2048 + cc * 128 + c];
        unsigned long long u;
        asm("mov.b64 %0, {%1, %2};" : "=l"(u) : "f"(w0), "f"(w1));
        s_w[c][p] = u;
    }
    __syncthreads();

    const float* xp = x4 + ((size_t)(b * CIN + cc * 128)) * NN + n;
    unsigned long long a0 = 0ull, a1 = 0ull, a2 = 0ull, a3 = 0ull;

#pragma unroll 16
    for (int c = 0; c < 128; c++) {
        float v = xp[(size_t)c * NN];
        unsigned long long vv;
        asm("mov.b64 %0, {%1, %1};" : "=l"(vv) : "f"(v));
        ulonglong2 wA = *(const ulonglong2*)&s_w[c][0];
        ulonglong2 wB = *(const ulonglong2*)&s_w[c][2];
        asm("fma.rn.f32x2 %0, %1, %2, %0;" : "+l"(a0) : "l"(vv), "l"(wA.x));
        asm("fma.rn.f32x2 %0, %1, %2, %0;" : "+l"(a1) : "l"(vv), "l"(wA.y));
        asm("fma.rn.f32x2 %0, %1, %2, %0;" : "+l"(a2) : "l"(vv), "l"(wB.x));
        asm("fma.rn.f32x2 %0, %1, %2, %0;" : "+l"(a3) : "l"(vv), "l"(wB.y));
    }
    unsigned long long* out =
        (unsigned long long*)(g_fea_part + ((size_t)((b * 16 + cc) * NN + n)) * 8);
    out[0] = a0; out[1] = a1; out[2] = a2; out[3] = a3;
}

// ---------------- kernel 2: fused GAT1 + GAT2 -> fp16 flat ----------------
__global__ void gat_kernel(const float* __restrict__ pb,
                           const float* __restrict__ W1, const float* __restrict__ a1s,
                           const float* __restrict__ a1d, const float* __restrict__ b1,
                           const float* __restrict__ W2, const float* __restrict__ a2s,
                           const float* __restrict__ a2d, const float* __restrict__ b2) {
    extern __shared__ float sm[];
    float* h1  = sm;
    float* h2s = h1 + 64 * NN;
    float* as1 = h2s + NN * 9;
    float* as2 = as1 + NN * 5;
    float* W1s = as2 + NN;
    float* W2s = W1s + 512;

    int b = blockIdx.x, n = threadIdx.x;
    for (int i = n; i < 512; i += blockDim.x) { W1s[i] = W1[i]; W2s[i] = W2[i]; }

    float fs[8];
#pragma unroll
    for (int k = 0; k < 8; k++) fs[k] = pb[k];
#pragma unroll
    for (int cc = 0; cc < 16; cc++) {
        const float* fp = g_fea_part + ((size_t)((b * 16 + cc) * NN + n)) * 8;
#pragma unroll
        for (int k = 0; k < 8; k++) fs[k] += fp[k];
    }
    __syncthreads();

    float ad1[4];
    {
        float as[4];
#pragma unroll
        for (int h = 0; h < 4; h++) { as[h] = 0.f; ad1[h] = 0.f; }
#pragma unroll
        for (int f = 0; f < 64; f++) {
            float hv = 0.f;
#pragma unroll
            for (int k = 0; k < 8; k++) hv += fs[k] * W1s[k * 64 + f];
            h1[f * NN + n] = hv;
            int hd = f >> 4;
            as[hd] += hv * __ldg(&a1s[f]);
            ad1[hd] += hv * __ldg(&a1d[f]);
        }
#pragma unroll
        for (int h = 0; h < 4; h++) as1[n * 5 + h] = as[h];
    }
    __syncthreads();

    int i = n / WG, j = n % WG;
    int srcs[9]; float mask[9];
#pragma unroll
    for (int k = 0; k < 9; k++) {
        int di = k / 3 - 1, dj = k % 3 - 1;
        int ni = i + di, nj = j + dj;
        bool v = (ni >= 0 && ni < HG && nj >= 0 && nj < WG);
        srcs[k] = v ? ni * WG + nj : n;
        mask[k] = v ? 0.f : -1e30f;
    }

    float h2[8];
#pragma unroll
    for (int o = 0; o < 8; o++) h2[o] = 0.f;

#pragma unroll
    for (int hd = 0; hd < 4; hd++) {
        float ek[9], m = -1e30f;
#pragma unroll
        for (int k = 0; k < 9; k++) {
            float e = as1[srcs[k] * 5 + hd] + ad1[hd];
            e = e > 0.f ? e : 0.2f * e;
            e += mask[k];
            ek[k] = e; m = fmaxf(m, e);
        }
        float s = 0.f;
#pragma unroll
        for (int k = 0; k < 9; k++) { ek[k] = __expf(ek[k] - m); s += ek[k]; }
        float inv = 1.f / s;

        float acc[16];
#pragma unroll
        for (int d = 0; d < 16; d++) acc[d] = 0.f;
#pragma unroll
        for (int k = 0; k < 9; k++) {
            float w = ek[k] * inv;
            const float* hp = &h1[(hd * 16) * NN + srcs[k]];
#pragma unroll
            for (int d = 0; d < 16; d++) acc[d] += w * hp[d * NN];
        }
#pragma unroll
        for (int d = 0; d < 16; d++) {
            int f = hd * 16 + d;
            float x1 = fmaxf(acc[d] + __ldg(&b1[f]), 0.f);
#pragma unroll
            for (int o = 0; o < 8; o++) h2[o] += x1 * W2s[f * 8 + o];
        }
    }

    float ad2 = 0.f;
    {
        float a = 0.f;
#pragma unroll
        for (int o = 0; o < 8; o++) {
            h2s[n * 9 + o] = h2[o];
            a   += h2[o] * __ldg(&a2s[o]);
            ad2 += h2[o] * __ldg(&a2d[o]);
        }
        as2[n] = a;
    }
    __syncthreads();

    {
        float ek[9], m = -1e30f;
#pragma unroll
        for (int k = 0; k < 9; k++) {
            float e = as2[srcs[k]] + ad2;
            e = e > 0.f ? e : 0.2f * e;
            e += mask[k];
            ek[k] = e; m = fmaxf(m, e);
        }
        float s = 0.f;
#pragma unroll
        for (int k = 0; k < 9; k++) { ek[k] = __expf(ek[k] - m); s += ek[k]; }
        float inv = 1.f / s;

        float acc2[8];
#pragma unroll
        for (int o = 0; o < 8; o++) acc2[o] = 0.f;
#pragma unroll
        for (int k = 0; k < 9; k++) {
            float w = ek[k] * inv;
            const float* hp = &h2s[srcs[k] * 9];
#pragma unroll
            for (int o = 0; o < 8; o++) acc2[o] += w * hp[o];
        }
        size_t base = (size_t)b * KPAD1 + n * 8;
#pragma unroll
        for (int o = 0; o < 8; o++)
            g_flat_h[base + o] = __float2half(acc2[o] + __ldg(&b2[o]));
        if (n < 56)
            g_flat_h[(size_t)b * KPAD1 + 1800 + n] = __float2half(0.f);
    }
}

// ---------------- HMMA GEMM: single-pass fp16, 128x128 tile, split-K partial --------
#define A_STR 80
#define B_STR 272
#define STG_SZ (128 * A_STR + 32 * B_STR)               // 18944
#define OFF_A(s) ((s) * STG_SZ)
#define OFF_B(s) ((s) * STG_SZ + 128 * A_STR)
#define GEMM_SMEM (2 * STG_SZ)                          // 37888

__device__ __forceinline__ void ldm_x4(uint32_t* r, uint32_t addr) {
    asm volatile("ldmatrix.sync.aligned.m8n8.x4.shared.b16 {%0,%1,%2,%3}, [%4];"
                 : "=r"(r[0]), "=r"(r[1]), "=r"(r[2]), "=r"(r[3]) : "r"(addr));
}
__device__ __forceinline__ void ldm_x4t(uint32_t* r, uint32_t addr) {
    asm volatile("ldmatrix.sync.aligned.m8n8.x4.trans.shared.b16 {%0,%1,%2,%3}, [%4];"
                 : "=r"(r[0]), "=r"(r[1]), "=r"(r[2]), "=r"(r[3]) : "r"(addr));
}
__device__ __forceinline__ void mma16816(float* c, const uint32_t* a, uint32_t b0, uint32_t b1) {
    asm volatile("mma.sync.aligned.m16n8k16.row.col.f32.f16.f16.f32 "
                 "{%0,%1,%2,%3}, {%4,%5,%6,%7}, {%8,%9}, {%0,%1,%2,%3};"
                 : "+f"(c[0]), "+f"(c[1]), "+f"(c[2]), "+f"(c[3])
                 : "r"(a[0]), "r"(a[1]), "r"(a[2]), "r"(a[3]), "r"(b0), "r"(b1));
}

__global__ void __launch_bounds__(256, 2) mma_gemm(
    const __half* __restrict__ A, int lda,
    const float* __restrict__ B, int ldb, int Krows, int Ntot, int total_iters,
    float* __restrict__ part) {
    extern __shared__ char smc[];
    uint32_t sb = smem_u32(smc);
    int t = threadIdx.x, wid = t >> 5, lane = t & 31;
    int n0 = blockIdx.x * 128;

    int it_begin, it_count;
    {
        int sp = blockIdx.y, nsp = gridDim.y;
        int base = total_iters / nsp, rem = total_iters % nsp;
        it_count = base + (sp < rem ? 1 : 0);
        it_begin = sp * base + (sp < rem ? sp : rem);
    }

    int arow = t >> 1, ahalf = t & 1;          // A: 128 rows x 64 B, 2 x 16B per thread
    int brow = t >> 3, bg = t & 7;             // B: 32 rows x 8 col-groups

    float acc[64];
#pragma unroll
    for (int c = 0; c < 64; c++) acc[c] = 0.f;

    uint4 pa[2];
    float4 pb[4];

    auto load_regs = [&](int it_rel) {
        int k0 = (it_begin + it_rel) * 32;
        const char* ga = (const char*)(A + (size_t)arow * lda + k0) + ahalf * 32;
        pa[0] = *(const uint4*)ga;  pa[1] = *(const uint4*)(ga + 16);
        int kg = k0 + brow;
        bool okk = kg < Krows;
        const float* brp = B + (size_t)kg * ldb + n0;
#pragma unroll
        for (int cc = 0; cc < 4; cc++) {
            int col = bg * 4 + cc * 32;
            bool ok = okk && (n0 + col < Ntot);
            pb[cc] = ok ? *(const float4*)(brp + col) : make_float4(0.f, 0.f, 0.f, 0.f);
        }
    };
    auto store_smem = [&](int s) {
        uint32_t ab = arow * A_STR + ahalf * 32;
        *(uint4*)(smc + OFF_A(s) + ab) = pa[0];
        *(uint4*)(smc + OFF_A(s) + ab + 16) = pa[1];
#pragma unroll
        for (int cc = 0; cc < 4; cc++) {
            int col = bg * 4 + cc * 32;
            float4 v = pb[cc];
            union { __half h[4]; uint2 u; } uh;
            uh.h[0] = __float2half(v.x); uh.h[1] = __float2half(v.y);
            uh.h[2] = __float2half(v.z); uh.h[3] = __float2half(v.w);
            *(uint2*)(smc + OFF_B(s) + brow * B_STR + col * 2) = uh.u;
        }
    };

    load_regs(0);
    store_smem(0);
    __syncthreads();

    int wm = wid >> 1, wn = wid & 1;
    int m0 = wm * 32;
    int lrow = lane & 15, lsel = lane >> 4;

    for (int it = 0; it < it_count; it++) {
        int buf = it & 1;
        if (it + 1 < it_count) load_regs(it + 1);

        uint32_t aoff = (m0 + lrow) * A_STR + lsel * 16;
#pragma unroll
        for (int ks = 0; ks < 2; ks++) {
            uint32_t ah[2][4];
            ldm_x4(ah[0], sb + OFF_A(buf) + aoff + ks * 32);
            ldm_x4(ah[1], sb + OFF_A(buf) + aoff + 16 * A_STR + ks * 32);
            uint32_t boff = (ks * 16 + lrow) * B_STR + wn * 128 + lsel * 16;

            uint32_t bf[2][4];
            ldm_x4t(bf[0], sb + OFF_B(buf) + boff);
#pragma unroll
            for (int jj = 0; jj < 4; jj++) {
                int cur = jj & 1;
                if (jj < 3)
                    ldm_x4t(bf[cur ^ 1], sb + OFF_B(buf) + boff + (jj + 1) * 32);
                const uint32_t* bh = bf[cur];
                float* c00 = acc + ((0 * 4 + jj) * 2 + 0) * 4;
                float* c01 = acc + ((0 * 4 + jj) * 2 + 1) * 4;
                float* c10 = acc + ((1 * 4 + jj) * 2 + 0) * 4;
                float* c11 = acc + ((1 * 4 + jj) * 2 + 1) * 4;
                mma16816(c00, ah[0], bh[0], bh[1]);
                mma16816(c01, ah[0], bh[2], bh[3]);
                mma16816(c10, ah[1], bh[0], bh[1]);
                mma16816(c11, ah[1], bh[2], bh[3]);
            }
        }

        if (it + 1 < it_count) store_smem(buf ^ 1);
        __syncthreads();
    }

    // epilogue: fp32 partial to part[split][128][Ntot]
    int g = lane >> 2, tg = lane & 3;
    float* dst = part + (size_t)blockIdx.y * BATCH * (size_t)Ntot;
#pragma unroll
    for (int mh = 0; mh < 2; mh++) {
#pragma unroll
        for (int jj = 0; jj < 4; jj++) {
#pragma unroll
            for (int nb = 0; nb < 2; nb++) {
                const float* a4 = acc + ((mh * 4 + jj) * 2 + nb) * 4;
                int col = n0 + wn * 64 + jj * 16 + nb * 8 + tg * 2;
                if (col >= Ntot) continue;
                int m = wm * 32 + mh * 16 + g;
                *(float2*)(dst + (size_t)m * Ntot + col) = make_float2(a4[0], a4[1]);
                *(float2*)(dst + (size_t)(m + 8) * Ntot + col) = make_float2(a4[2], a4[3]);
            }
        }
    }
}

// ---------------- fc1 reduce: 8 partials + bias + relu -> fp16 ----------------
__global__ void reduce_kernel(const float* __restrict__ b1) {
    int slot = blockIdx.x * 256 + threadIdx.x;
    const float4* P = (const float4*)g_part;
    float4 v = P[slot];
#pragma unroll
    for (int s = 1; s < SPLITS1; s++) {
        float4 u = P[(size_t)s * (BATCH * N1 / 4) + slot];
        v.x += u.x; v.y += u.y; v.z += u.z; v.w += u.w;
    }
    int base = slot * 4, col = base & (N1 - 1);
    v.x = fmaxf(v.x + __ldg(&b1[col]), 0.f);
    v.y = fmaxf(v.y + __ldg(&b1[col + 1]), 0.f);
    v.z = fmaxf(v.z + __ldg(&b1[col + 2]), 0.f);
    v.w = fmaxf(v.w + __ldg(&b1[col + 3]), 0.f);
    union { __half h[4]; uint2 u; } uh;
    uh.h[0] = __float2half(v.x); uh.h[1] = __float2half(v.y);
    uh.h[2] = __float2half(v.z); uh.h[3] = __float2half(v.w);
    *(uint2*)(g_hid_h + base) = uh.u;
}

// ---------------- fc2 reduce: 2 partials + bias -> fp32 out ----------------
__global__ void reduce2_kernel(const float* __restrict__ b2, float* __restrict__ out) {
    int slot = blockIdx.x * 256 + threadIdx.x;
    const float4* P = (const float4*)g_part2;
    float4 v = P[slot];
    float4 u = P[(size_t)(BATCH * N2 / 4) + slot];
    v.x += u.x; v.y += u.y; v.z += u.z; v.w += u.w;
    int base = slot * 4;
    int col = base % N2;
    v.x += __ldg(&b2[col]);
    v.y += __ldg(&b2[col + 1]);
    v.z += __ldg(&b2[col + 2]);
    v.w += __ldg(&b2[col + 3]);
    *(float4*)(out + base) = v;
}

// ---------------- launcher ----------------
extern "C" void kernel_launch(void* const* d_in, const int* in_sizes, int n_in,
                              void* d_out, int out_size) {
    const float* x4     = (const float*)d_in[0];
    const float* pool_w = (const float*)d_in[1];
    const float* pool_b = (const float*)d_in[2];
    const float* g1w    = (const float*)d_in[3];
    const float* g1as   = (const float*)d_in[4];
    const float* g1ad   = (const float*)d_in[5];
    const float* g1b    = (const float*)d_in[6];
    const float* g2w    = (const float*)d_in[7];
    const float* g2as   = (const float*)d_in[8];
    const float* g2ad   = (const float*)d_in[9];
    const float* g2b    = (const float*)d_in[10];
    const float* w1     = (const float*)d_in[11];
    const float* b1     = (const float*)d_in[12];
    const float* w2     = (const float*)d_in[13];
    const float* b2     = (const float*)d_in[14];
    float* out = (float*)d_out;

    const int gat_smem = (64 * NN + NN * 9 + NN * 5 + NN + 1024) * (int)sizeof(float);
    cudaFuncSetAttribute(gat_kernel, cudaFuncAttributeMaxDynamicSharedMemorySize, gat_smem);
    cudaFuncSetAttribute(mma_gemm, cudaFuncAttributeMaxDynamicSharedMemorySize, GEMM_SMEM);

    __half *fh, *hh;
    float *p1, *p2;
    cudaGetSymbolAddress((void**)&fh, g_flat_h);
    cudaGetSymbolAddress((void**)&hh, g_hid_h);
    cudaGetSymbolAddress((void**)&p1, g_part);
    cudaGetSymbolAddress((void**)&p2, g_part2);

    pool_kernel<<<dim3(128, 16), 225>>>(x4, pool_w);
    gat_kernel<<<128, 225, gat_smem>>>(pool_b, g1w, g1as, g1ad, g1b, g2w, g2as, g2ad, g2b);
    mma_gemm<<<dim3(N1 / 128, SPLITS1), 256, GEMM_SMEM>>>(
        fh, KPAD1, w1, N1, 1800, N1, NITER1, p1);
    reduce_kernel<<<BATCH * N1 / 1024, 256>>>(b1);
    mma_gemm<<<dim3((N2 + 127) / 128, SPLITS2), 256, GEMM_SMEM>>>(
        hh, K2, w2, N2, K2, N2, NITER2, p2);
    reduce2_kernel<<<BATCH * N2 / 1024, 256>>>(b2, out);
}